// round 6
// baseline (speedup 1.0000x reference)
#include <cuda_runtime.h>
#include <cstdint>

// Problem constants (from reference setup_inputs)
#define BATCH 16
#define CCH   64
#define HH    64
#define WW    64
#define QQ    8192
#define BQ    131072          // BATCH*QQ
#define NPIX  65536           // BATCH*HH*WW
#define HID   256
#define KDIM  576             // CCH*9

typedef unsigned long long ull;

// Scratch (static __device__ arrays: allocation-free per harness rules)
__device__ float g_h1[(size_t)BQ * HID];     // layer-1 activations
__device__ float g_h2[(size_t)BQ * HID];     // layer-2 activations
__device__ float g_v[(size_t)NPIX * HID];    // per-pixel  v[p,h] = sum_k featu[p,k]*w3[h,k]
__device__ float g_s[NPIX];                  // per-pixel  s[p]   = b3 . featu[p,:]
__device__ int   g_pix[BQ];                  // query -> global pixel index
__device__ float g_w3t[KDIM * HID];          // w3 reordered: [pp*64+c][h]

// ---------- packed f32x2 helpers ----------
__device__ __forceinline__ ull fma2(ull a, ull b, ull c) {
    ull d;
    asm("fma.rn.f32x2 %0, %1, %2, %3;" : "=l"(d) : "l"(a), "l"(b), "l"(c));
    return d;
}
__device__ __forceinline__ ull pack2(float x, float y) {
    ull d;
    asm("mov.b64 %0, {%1, %2};" : "=l"(d) : "f"(x), "f"(y));
    return d;
}
__device__ __forceinline__ float2 unpack2(ull v) {
    float2 r;
    asm("mov.b64 {%0, %1}, %2;" : "=f"(r.x), "=f"(r.y) : "l"(v));
    return r;
}

// ---------- kernel 1: per-query prep + fused layer 1 ----------
// grid = BQ blocks, 256 threads; thread j computes h1[q][j]
__global__ void __launch_bounds__(256)
k_prep(const float* __restrict__ coord, const float* __restrict__ cell,
       const float* __restrict__ w1, const float* __restrict__ b1) {
    int q = blockIdx.x;
    int j = threadIdx.x;
    int b = q >> 13;   // q / 8192

    float cy = coord[q * 2 + 0], cx = coord[q * 2 + 1];
    float ly = cell[q * 2 + 0],  lx = cell[q * 2 + 1];
    float sy = cy - ly * 0.5f;
    float sx = cx - lx * 0.5f;
    const float eps = 1e-6f;
    const float lo = -1.0f + 1e-6f, hi = 1.0f - 1e-6f;
    float qyc = fminf(fmaxf(sy + eps, lo), hi);
    float qxc = fminf(fmaxf(sx + eps, lo), hi);
    // ((c+1)*S - 1)/2, round half-even (matches jnp.round), clamp
    float fy = ((qyc + 1.0f) * 64.0f - 1.0f) * 0.5f;
    float fx = ((qxc + 1.0f) * 64.0f - 1.0f) * 0.5f;
    int iy = (int)rintf(fy); iy = min(max(iy, 0), 63);
    int ix = (int)rintf(fx); ix = min(max(ix, 0), 63);

    float qy = (float)iy * 0.03125f - 1.0f;   // 2*iy/64 - 1 (exact)
    float qx = (float)ix * 0.03125f - 1.0f;
    float rel_y = (sy - qy) * 32.0f;
    float rel_x = (sx - qx) * 32.0f;
    float rr    = ly * 32.0f;

    float h = rel_y * w1[j] + rel_x * w1[256 + j] + rr * w1[512 + j] + b1[j];
    g_h1[(size_t)q * HID + j] = fmaxf(h, 0.0f);

    if (j == 0) g_pix[q] = b * 4096 + iy * 64 + ix;
}

// ---------- kernel 2: reorder w3 -> w3t[pp*64+c][h] ----------
__global__ void __launch_bounds__(256)
k_w3t(const float* __restrict__ w3) {
    int kp = blockIdx.x;      // 0..575
    int n  = threadIdx.x;     // 0..255
    int pp = kp >> 6;
    int c  = kp & 63;
    g_w3t[kp * HID + n] = w3[n * KDIM + c * 9 + pp];
}

// ---------- kernel 3: s[p] = b3 . featu[p,:]  (1-channel 3x3 conv) ----------
__global__ void __launch_bounds__(256)
k_sconv(const float* __restrict__ feat, const float* __restrict__ b3) {
    int pm = blockIdx.x * 256 + threadIdx.x;   // 0..65535
    int b = pm >> 12, rem = pm & 4095, y = rem >> 6, x = rem & 63;
    float acc = 0.0f;
    for (int c = 0; c < CCH; c++) {
        const float* f = feat + ((size_t)(b * CCH + c)) * 4096;
        #pragma unroll
        for (int pp = 0; pp < 9; pp++) {
            int dy = pp / 3 - 1, dx = pp % 3 - 1;
            int sy = y + dy, sx = x + dx;
            if (sy >= 0 && sy < 64 && sx >= 0 && sx < 64)
                acc += f[sy * 64 + sx] * b3[c * 9 + pp];
        }
    }
    g_s[pm] = acc;
}

// ---------- GEMM tiling parameters ----------
#define BM 128
#define BN 128
#define BK 8

// ---------- kernel 4: implicit-GEMM 3x3 conv: g_v[p,h] ----------
// M = 65536 pixels, N = 256, K = 576 ordered (pp, c)
__global__ void __launch_bounds__(256)
k_conv(const float* __restrict__ feat) {
    __shared__ float As[BK][BM];
    __shared__ float Bs[BK][BN];
    int tid = threadIdx.x;
    int n0 = blockIdx.x * BN;   // 0 or 128
    int m0 = blockIdx.y * BM;

    // A-load mapping: 128 pixels x 2 channel-groups (4 channels each)
    int px = tid & 127;
    int cg = tid >> 7;                 // 0..1
    int pm = m0 + px;
    int b = pm >> 12, rem = pm & 4095, y = rem >> 6, x = rem & 63;
    const float* fimg = feat + (size_t)b * (CCH * 4096);

    // B-load mapping
    int brow = tid >> 5;               // 0..7
    int bcol = (tid & 31) * 4;

    int ty = tid >> 4, tx = tid & 15;

    ull acc[8][4];
    #pragma unroll
    for (int i = 0; i < 8; i++)
        #pragma unroll
        for (int j = 0; j < 4; j++) acc[i][j] = 0ull;

    for (int pp = 0; pp < 9; pp++) {
        int dy = pp / 3 - 1, dx = pp % 3 - 1;
        int sy = y + dy, sx = x + dx;
        bool ok = (sy >= 0 && sy < 64 && sx >= 0 && sx < 64);
        const float* fbase = fimg + sy * 64 + sx;   // + c*4096 per channel

        for (int c0 = 0; c0 < CCH; c0 += BK) {
            #pragma unroll
            for (int i = 0; i < 4; i++) {
                int cc = cg * 4 + i;
                As[cc][px] = ok ? fbase[(c0 + cc) * 4096] : 0.0f;
            }
            float4 bv = *(const float4*)&g_w3t[(pp * 64 + c0 + brow) * HID + n0 + bcol];
            *(float4*)&Bs[brow][bcol] = bv;
            __syncthreads();

            #pragma unroll
            for (int kk = 0; kk < BK; kk++) {
                float4 a0 = *(float4*)&As[kk][ty * 8];
                float4 a1 = *(float4*)&As[kk][ty * 8 + 4];
                float4 b0 = *(float4*)&Bs[kk][tx * 8];
                float4 b1 = *(float4*)&Bs[kk][tx * 8 + 4];
                ull bp0 = pack2(b0.x, b0.y), bp1 = pack2(b0.z, b0.w);
                ull bp2 = pack2(b1.x, b1.y), bp3 = pack2(b1.z, b1.w);
                float aa[8] = {a0.x, a0.y, a0.z, a0.w, a1.x, a1.y, a1.z, a1.w};
                #pragma unroll
                for (int i = 0; i < 8; i++) {
                    ull ad = pack2(aa[i], aa[i]);
                    acc[i][0] = fma2(ad, bp0, acc[i][0]);
                    acc[i][1] = fma2(ad, bp1, acc[i][1]);
                    acc[i][2] = fma2(ad, bp2, acc[i][2]);
                    acc[i][3] = fma2(ad, bp3, acc[i][3]);
                }
            }
            __syncthreads();
        }
    }

    #pragma unroll
    for (int i = 0; i < 8; i++) {
        int row = m0 + ty * 8 + i;
        float2 c0 = unpack2(acc[i][0]);
        float2 c1 = unpack2(acc[i][1]);
        float2 c2 = unpack2(acc[i][2]);
        float2 c3 = unpack2(acc[i][3]);
        float4 o0 = make_float4(c0.x, c0.y, c1.x, c1.y);
        float4 o1 = make_float4(c2.x, c2.y, c3.x, c3.y);
        *(float4*)&g_v[(size_t)row * HID + n0 + tx * 8]     = o0;
        *(float4*)&g_v[(size_t)row * HID + n0 + tx * 8 + 4] = o1;
    }
}

// ---------- kernel 5: h2 = relu(h1 @ w2 + b2) ----------
// M = 131072, N = 256, K = 256
__global__ void __launch_bounds__(256)
k_gemm_h2(const float* __restrict__ w2, const float* __restrict__ b2) {
    __shared__ float As[BK][BM];
    __shared__ float Bs[BK][BN];
    int tid = threadIdx.x;
    int n0 = blockIdx.x * BN;
    int m0 = blockIdx.y * BM;

    int arow = tid >> 1;
    int acol = (tid & 1) * 4;
    int brow = tid >> 5;
    int bcol = (tid & 31) * 4;
    int ty = tid >> 4, tx = tid & 15;

    ull acc[8][4];
    #pragma unroll
    for (int i = 0; i < 8; i++)
        #pragma unroll
        for (int j = 0; j < 4; j++) acc[i][j] = 0ull;

    for (int k0 = 0; k0 < HID; k0 += BK) {
        float4 av = *(const float4*)&g_h1[(size_t)(m0 + arow) * HID + k0 + acol];
        As[acol + 0][arow] = av.x;
        As[acol + 1][arow] = av.y;
        As[acol + 2][arow] = av.z;
        As[acol + 3][arow] = av.w;
        float4 bv = *(const float4*)&w2[(k0 + brow) * HID + n0 + bcol];
        *(float4*)&Bs[brow][bcol] = bv;
        __syncthreads();

        #pragma unroll
        for (int kk = 0; kk < BK; kk++) {
            float4 a0 = *(float4*)&As[kk][ty * 8];
            float4 a1 = *(float4*)&As[kk][ty * 8 + 4];
            float4 b0 = *(float4*)&Bs[kk][tx * 8];
            float4 b1 = *(float4*)&Bs[kk][tx * 8 + 4];
            ull bp0 = pack2(b0.x, b0.y), bp1 = pack2(b0.z, b0.w);
            ull bp2 = pack2(b1.x, b1.y), bp3 = pack2(b1.z, b1.w);
            float aa[8] = {a0.x, a0.y, a0.z, a0.w, a1.x, a1.y, a1.z, a1.w};
            #pragma unroll
            for (int i = 0; i < 8; i++) {
                ull ad = pack2(aa[i], aa[i]);
                acc[i][0] = fma2(ad, bp0, acc[i][0]);
                acc[i][1] = fma2(ad, bp1, acc[i][1]);
                acc[i][2] = fma2(ad, bp2, acc[i][2]);
                acc[i][3] = fma2(ad, bp3, acc[i][3]);
            }
        }
        __syncthreads();
    }

    float bn[8];
    #pragma unroll
    for (int j = 0; j < 8; j++) bn[j] = b2[n0 + tx * 8 + j];

    #pragma unroll
    for (int i = 0; i < 8; i++) {
        int row = m0 + ty * 8 + i;
        float2 c0 = unpack2(acc[i][0]);
        float2 c1 = unpack2(acc[i][1]);
        float2 c2 = unpack2(acc[i][2]);
        float2 c3 = unpack2(acc[i][3]);
        float4 o0 = make_float4(fmaxf(c0.x + bn[0], 0.f), fmaxf(c0.y + bn[1], 0.f),
                                fmaxf(c1.x + bn[2], 0.f), fmaxf(c1.y + bn[3], 0.f));
        float4 o1 = make_float4(fmaxf(c2.x + bn[4], 0.f), fmaxf(c2.y + bn[5], 0.f),
                                fmaxf(c3.x + bn[6], 0.f), fmaxf(c3.y + bn[7], 0.f));
        *(float4*)&g_h2[(size_t)row * HID + n0 + tx * 8]     = o0;
        *(float4*)&g_h2[(size_t)row * HID + n0 + tx * 8 + 4] = o1;
    }
}

// ---------- kernel 6: out[q] = s[p] + h2[q,:] . v[p,:] ----------
__global__ void __launch_bounds__(256)
k_out(float* __restrict__ out) {
    int warp = threadIdx.x >> 5;
    int lane = threadIdx.x & 31;
    int q = blockIdx.x * 8 + warp;
    int p = g_pix[q];
    const float4* hv = (const float4*)(g_h2 + (size_t)q * HID);
    const float4* vv = (const float4*)(g_v + (size_t)p * HID);
    float s = 0.0f;
    #pragma unroll
    for (int i = 0; i < 2; i++) {
        float4 a = hv[lane + i * 32];
        float4 b = vv[lane + i * 32];
        s += a.x * b.x + a.y * b.y + a.z * b.z + a.w * b.w;
    }
    #pragma unroll
    for (int o = 16; o; o >>= 1) s += __shfl_xor_sync(0xFFFFFFFFu, s, o);
    if (lane == 0) out[q] = g_s[p] + s;
}

extern "C" void kernel_launch(void* const* d_in, const int* in_sizes, int n_in,
                              void* d_out, int out_size) {
    const float* feat  = (const float*)d_in[0];
    const float* coord = (const float*)d_in[1];
    const float* cell  = (const float*)d_in[2];
    const float* w1    = (const float*)d_in[3];
    const float* b1    = (const float*)d_in[4];
    const float* w2    = (const float*)d_in[5];
    const float* b2    = (const float*)d_in[6];
    const float* w3    = (const float*)d_in[7];
    const float* b3    = (const float*)d_in[8];
    float* out = (float*)d_out;

    k_prep<<<BQ, 256>>>(coord, cell, w1, b1);
    k_w3t<<<KDIM, 256>>>(w3);
    k_sconv<<<NPIX / 256, 256>>>(feat, b3);
    k_conv<<<dim3(2, NPIX / BM), 256>>>(feat);
    k_gemm_h2<<<dim3(2, BQ / BM), 256>>>(w2, b2);
    k_out<<<BQ / 8, 256>>>(out);
}

// round 7
// speedup vs baseline: 1.2900x; 1.2900x over previous
#include <cuda_runtime.h>
#include <cuda_bf16.h>
#include <cstdint>

// Problem constants
#define BATCH 16
#define CCH   64
#define QQ    8192
#define BQ    131072          // BATCH*QQ
#define NPIX  65536           // BATCH*64*64
#define HID   256
#define KDIM  576             // CCH*9

// Smem tile strides (bf16 units): pad for conflict-free ldmatrix
#define SA 136                // A tile rows: 32 k x 128 m (+8 pad)
#define SB 264                // B tile rows: 32 k x 256 n (+8 pad)

// ---------------- scratch (static device arrays) ----------------
__device__ __nv_bfloat16 g_h1s[(size_t)512 * BQ];          // h1 split, k-major: rows 0-255 hi, 256-511 lo
__device__ float         g_h2 [(size_t)BQ * HID];          // layer-2 activations (fp32)
__device__ float         g_v  [(size_t)NPIX * HID];        // per-pixel v[p,h]
__device__ float         g_s  [NPIX];                      // per-pixel b3 . featu[p]
__device__ int           g_pix[BQ];                        // query -> pixel
__device__ __nv_bfloat16 g_fhi[(size_t)BATCH * CCH * 4096];
__device__ __nv_bfloat16 g_flo[(size_t)BATCH * CCH * 4096];
__device__ __nv_bfloat16 g_w2s[768 * 256];                 // rows: [w2hi ; w2lo ; w2hi]
__device__ __nv_bfloat16 g_w3s[1728 * 256];                // rows: [w3hi ; w3lo ; w3hi] (k = pp*64+c order)

// ---------------- mma / ldmatrix helpers ----------------
__device__ __forceinline__ void mma16816(float* c, const unsigned* a, const unsigned* b) {
    asm volatile("mma.sync.aligned.m16n8k16.row.col.f32.bf16.bf16.f32 "
                 "{%0,%1,%2,%3}, {%4,%5,%6,%7}, {%8,%9}, {%0,%1,%2,%3};"
                 : "+f"(c[0]), "+f"(c[1]), "+f"(c[2]), "+f"(c[3])
                 : "r"(a[0]), "r"(a[1]), "r"(a[2]), "r"(a[3]),
                   "r"(b[0]), "r"(b[1]));
}
__device__ __forceinline__ void ldsm4t(unsigned* r, uint32_t addr) {
    asm volatile("ldmatrix.sync.aligned.m8n8.x4.trans.shared.b16 {%0,%1,%2,%3}, [%4];"
                 : "=r"(r[0]), "=r"(r[1]), "=r"(r[2]), "=r"(r[3]) : "r"(addr));
}
__device__ __forceinline__ void split_bf16(float x, __nv_bfloat16& hi, __nv_bfloat16& lo) {
    hi = __float2bfloat16_rn(x);
    lo = __float2bfloat16_rn(x - __bfloat162float(hi));
}

// ---------------- kernel: feat -> hi/lo bf16 ----------------
__global__ void __launch_bounds__(256)
k_featsplit(const float* __restrict__ feat) {
    int idx = blockIdx.x * 256 + threadIdx.x;   // 0 .. 4194303
    float v = feat[idx];
    __nv_bfloat16 hi, lo; split_bf16(v, hi, lo);
    g_fhi[idx] = hi; g_flo[idx] = lo;
}

// ---------------- kernel: w2 -> [hi;lo;hi] (k-major [768][256]) ----------------
__global__ void __launch_bounds__(256)
k_w2split(const float* __restrict__ w2) {
    int idx = blockIdx.x * 256 + threadIdx.x;   // 0 .. 768*256-1
    int r = idx >> 8, n = idx & 255;
    int sr = r & 255;
    float v = w2[sr * 256 + n];
    __nv_bfloat16 hi, lo; split_bf16(v, hi, lo);
    g_w2s[idx] = (r >= 256 && r < 512) ? lo : hi;
}

// ---------------- kernel: w3 -> [hi;lo;hi] reordered (k = pp*64+c) ----------------
__global__ void __launch_bounds__(256)
k_w3split(const float* __restrict__ w3) {
    int idx = blockIdx.x * 256 + threadIdx.x;   // 0 .. 1728*256-1
    int r = idx >> 8, n = idx & 255;
    int phase = (r >= 1152) ? 2 : (r >= 576 ? 1 : 0);
    int rr = r - phase * 576;
    int pp = rr >> 6, c = rr & 63;
    float v = w3[n * KDIM + c * 9 + pp];        // w3: [HID][576]
    __nv_bfloat16 hi, lo; split_bf16(v, hi, lo);
    g_w3s[idx] = (phase == 1) ? lo : hi;
}

// ---------------- kernel: per-query prep + layer 1 (split, k-major) ----------------
// grid (BQ/32, 32), 256 threads: lane group handles 32 queries, 8 hidden units / block-row
__global__ void __launch_bounds__(256)
k_prep(const float* __restrict__ coord, const float* __restrict__ cell,
       const float* __restrict__ w1, const float* __restrict__ b1) {
    int tid = threadIdx.x;
    int qi = tid & 31, jg = tid >> 5;
    int q = blockIdx.x * 32 + qi;
    int j = blockIdx.y * 8 + jg;
    int b = q >> 13;

    float cy = coord[q * 2 + 0], cx = coord[q * 2 + 1];
    float ly = cell[q * 2 + 0],  lx = cell[q * 2 + 1];
    float sy = cy - ly * 0.5f;
    float sx = cx - lx * 0.5f;
    const float eps = 1e-6f;
    const float lo_ = -1.0f + 1e-6f, hi_ = 1.0f - 1e-6f;
    float qyc = fminf(fmaxf(sy + eps, lo_), hi_);
    float qxc = fminf(fmaxf(sx + eps, lo_), hi_);
    float fy = ((qyc + 1.0f) * 64.0f - 1.0f) * 0.5f;
    float fx = ((qxc + 1.0f) * 64.0f - 1.0f) * 0.5f;
    int iy = (int)rintf(fy); iy = min(max(iy, 0), 63);
    int ix = (int)rintf(fx); ix = min(max(ix, 0), 63);

    float qy = (float)iy * 0.03125f - 1.0f;
    float qx = (float)ix * 0.03125f - 1.0f;
    float rel_y = (sy - qy) * 32.0f;
    float rel_x = (sx - qx) * 32.0f;
    float rr    = ly * 32.0f;

    float h = fmaxf(rel_y * w1[j] + rel_x * w1[256 + j] + rr * w1[512 + j] + b1[j], 0.0f);
    __nv_bfloat16 hh, hl; split_bf16(h, hh, hl);
    g_h1s[(size_t)j * BQ + q]         = hh;
    g_h1s[(size_t)(j + 256) * BQ + q] = hl;

    if (blockIdx.y == 0 && jg == 0) g_pix[q] = b * 4096 + iy * 64 + ix;
}

// ---------------- kernel: s[p] = b3 . featu[p,:] (fp32) ----------------
__global__ void __launch_bounds__(256)
k_sconv(const float* __restrict__ feat, const float* __restrict__ b3) {
    int pm = blockIdx.x * 256 + threadIdx.x;
    int b = pm >> 12, rem = pm & 4095, y = rem >> 6, x = rem & 63;
    float acc = 0.0f;
    for (int c = 0; c < CCH; c++) {
        const float* f = feat + ((size_t)(b * CCH + c)) * 4096;
        #pragma unroll
        for (int pp = 0; pp < 9; pp++) {
            int dy = pp / 3 - 1, dx = pp % 3 - 1;
            int sy = y + dy, sx = x + dx;
            if (sy >= 0 && sy < 64 && sx >= 0 && sx < 64)
                acc += f[sy * 64 + sx] * b3[c * 9 + pp];
        }
    }
    g_s[pm] = acc;
}

// ---------------- mma GEMM: conv  v[p,h] (M=65536, N=256, Keff=1728) ----------------
// CTA 128M x 256N, BK=32, 8 warps of 64x64 (Mf=4, Nf=8)
__global__ void __launch_bounds__(256, 1)
k_conv_mma() {
    __shared__ __align__(16) __nv_bfloat16 As[32 * SA];
    __shared__ __align__(16) __nv_bfloat16 Bs[32 * SB];
    int tid = threadIdx.x;
    int lane = tid & 31, wid = tid >> 5;
    int wm = (wid & 1) * 64, wn = (wid >> 1) * 64;
    int m0 = blockIdx.x * 128;

    // loader coords
    int kl = tid >> 3, seg = tid & 7;
    int mm = seg * 16;
    int pm = m0 + mm;
    int bimg = pm >> 12;
    int y = (pm >> 6) & 63;
    int x0 = mm & 63;

    float acc[4][8][4];
    #pragma unroll
    for (int i = 0; i < 4; i++)
        #pragma unroll
        for (int j = 0; j < 8; j++)
            #pragma unroll
            for (int k = 0; k < 4; k++) acc[i][j][k] = 0.f;

    __align__(16) __nv_bfloat16 stA[16];
    uint4 stB[4];

    const int NC = 54;
    // stage chunk 0
    {
        int ck = 0;
        int pp = 0;                     // phase 0, pp 0, c0 0
        int dy = -1, dx = -1; (void)pp;
        int c = kl;
        int syv = y + dy;
        bool yok = (unsigned)syv < 64u;
        const __nv_bfloat16* rowp = g_fhi + ((((size_t)bimg * CCH + c) * 64 + syv) << 6);
        #pragma unroll
        for (int i = 0; i < 16; i++) {
            int sxv = x0 + i + dx;
            __nv_bfloat16 v = __float2bfloat16(0.f);
            if (yok && (unsigned)sxv < 64u) v = rowp[sxv];
            stA[i] = v;
        }
        const uint4* pb = (const uint4*)(g_w3s + (size_t)(ck * 32 + kl) * 256 + seg * 32);
        stB[0] = pb[0]; stB[1] = pb[1]; stB[2] = pb[2]; stB[3] = pb[3];
    }

    uint32_t asb = (uint32_t)__cvta_generic_to_shared(As);
    uint32_t bsb = (uint32_t)__cvta_generic_to_shared(Bs);
    int t = lane >> 3, r8 = lane & 7;

    for (int ck = 0; ck < NC; ck++) {
        // commit staged chunk to smem
        uint4* da = (uint4*)(As + kl * SA + seg * 16);
        da[0] = *(const uint4*)&stA[0];
        da[1] = *(const uint4*)&stA[8];
        uint4* db = (uint4*)(Bs + kl * SB + seg * 32);
        db[0] = stB[0]; db[1] = stB[1]; db[2] = stB[2]; db[3] = stB[3];
        __syncthreads();

        // prefetch next chunk
        if (ck + 1 < NC) {
            int cn = ck + 1;
            int phase = cn >= 36 ? 2 : (cn >= 18 ? 1 : 0);
            int rem = cn - phase * 18;
            int pp = rem >> 1, c0 = (rem & 1) << 5;
            const __nv_bfloat16* src = (phase == 2) ? g_flo : g_fhi;
            int dy = pp / 3 - 1, dx = pp % 3 - 1;
            int c = c0 + kl;
            int syv = y + dy;
            bool yok = (unsigned)syv < 64u;
            const __nv_bfloat16* rowp = src + ((((size_t)bimg * CCH + c) * 64 + syv) << 6);
            #pragma unroll
            for (int i = 0; i < 16; i++) {
                int sxv = x0 + i + dx;
                __nv_bfloat16 v = __float2bfloat16(0.f);
                if (yok && (unsigned)sxv < 64u) v = rowp[sxv];
                stA[i] = v;
            }
            const uint4* pb = (const uint4*)(g_w3s + (size_t)(cn * 32 + kl) * 256 + seg * 32);
            stB[0] = pb[0]; stB[1] = pb[1]; stB[2] = pb[2]; stB[3] = pb[3];
        }

        // compute
        #pragma unroll
        for (int kk = 0; kk < 2; kk++) {
            int kb = kk * 16;
            unsigned afr[4][4], bfr[4][4];
            #pragma unroll
            for (int mf = 0; mf < 4; mf++) {
                int krow = kb + ((t >> 1) << 3) + r8;
                int mcol = wm + mf * 16 + ((t & 1) << 3);
                ldsm4t(afr[mf], asb + (uint32_t)(krow * SA + mcol) * 2u);
            }
            #pragma unroll
            for (int j = 0; j < 4; j++) {
                int krow = kb + ((t & 1) << 3) + r8;
                int ncol = wn + j * 16 + ((t >> 1) << 3);
                ldsm4t(bfr[j], bsb + (uint32_t)(krow * SB + ncol) * 2u);
            }
            #pragma unroll
            for (int mf = 0; mf < 4; mf++)
                #pragma unroll
                for (int nf = 0; nf < 8; nf++)
                    mma16816(acc[mf][nf], afr[mf], &bfr[nf >> 1][(nf & 1) * 2]);
        }
        __syncthreads();
    }

    // epilogue: write v (fp32)
    int g = lane >> 2, tc = (lane & 3) * 2;
    #pragma unroll
    for (int mf = 0; mf < 4; mf++) {
        #pragma unroll
        for (int nf = 0; nf < 8; nf++) {
            int r = m0 + wm + mf * 16 + g;
            int c = wn + nf * 8 + tc;
            float2 v0 = make_float2(acc[mf][nf][0], acc[mf][nf][1]);
            float2 v1 = make_float2(acc[mf][nf][2], acc[mf][nf][3]);
            *(float2*)&g_v[(size_t)r * 256 + c]       = v0;
            *(float2*)&g_v[(size_t)(r + 8) * 256 + c] = v1;
        }
    }
}

// ---------------- mma GEMM: h2 = relu(h1 @ w2 + b2) (M=131072, N=256, Keff=768) ----------------
__global__ void __launch_bounds__(256, 1)
k_h2_mma(const float* __restrict__ b2) {
    __shared__ __align__(16) __nv_bfloat16 As[32 * SA];
    __shared__ __align__(16) __nv_bfloat16 Bs[32 * SB];
    int tid = threadIdx.x;
    int lane = tid & 31, wid = tid >> 5;
    int wm = (wid & 1) * 64, wn = (wid >> 1) * 64;
    int m0 = blockIdx.x * 128;
    int kl = tid >> 3, seg = tid & 7;

    float acc[4][8][4];
    #pragma unroll
    for (int i = 0; i < 4; i++)
        #pragma unroll
        for (int j = 0; j < 8; j++)
            #pragma unroll
            for (int k = 0; k < 4; k++) acc[i][j][k] = 0.f;

    uint4 stA[2], stB[4];
    const int NC = 24;
    {
        // chunk 0: phase 0 → a_row0 = 0
        const uint4* pa = (const uint4*)(g_h1s + (size_t)kl * BQ + m0 + seg * 16);
        stA[0] = pa[0]; stA[1] = pa[1];
        const uint4* pb = (const uint4*)(g_w2s + (size_t)kl * 256 + seg * 32);
        stB[0] = pb[0]; stB[1] = pb[1]; stB[2] = pb[2]; stB[3] = pb[3];
    }

    uint32_t asb = (uint32_t)__cvta_generic_to_shared(As);
    uint32_t bsb = (uint32_t)__cvta_generic_to_shared(Bs);
    int t = lane >> 3, r8 = lane & 7;

    for (int ck = 0; ck < NC; ck++) {
        uint4* da = (uint4*)(As + kl * SA + seg * 16);
        da[0] = stA[0]; da[1] = stA[1];
        uint4* db = (uint4*)(Bs + kl * SB + seg * 32);
        db[0] = stB[0]; db[1] = stB[1]; db[2] = stB[2]; db[3] = stB[3];
        __syncthreads();

        if (ck + 1 < NC) {
            int cn = ck + 1;
            int phase = cn >> 3;
            int local = (cn & 7) * 32;
            int a_row0 = (phase == 2 ? 256 : 0) + local;
            const uint4* pa = (const uint4*)(g_h1s + (size_t)(a_row0 + kl) * BQ + m0 + seg * 16);
            stA[0] = pa[0]; stA[1] = pa[1];
            const uint4* pb = (const uint4*)(g_w2s + (size_t)(cn * 32 + kl) * 256 + seg * 32);
            stB[0] = pb[0]; stB[1] = pb[1]; stB[2] = pb[2]; stB[3] = pb[3];
        }

        #pragma unroll
        for (int kk = 0; kk < 2; kk++) {
            int kb = kk * 16;
            unsigned afr[4][4], bfr[4][4];
            #pragma unroll
            for (int mf = 0; mf < 4; mf++) {
                int krow = kb + ((t >> 1) << 3) + r8;
                int mcol = wm + mf * 16 + ((t & 1) << 3);
                ldsm4t(afr[mf], asb + (uint32_t)(krow * SA + mcol) * 2u);
            }
            #pragma unroll
            for (int j = 0; j < 4; j++) {
                int krow = kb + ((t & 1) << 3) + r8;
                int ncol = wn + j * 16 + ((t >> 1) << 3);
                ldsm4t(bfr[j], bsb + (uint32_t)(krow * SB + ncol) * 2u);
            }
            #pragma unroll
            for (int mf = 0; mf < 4; mf++)
                #pragma unroll
                for (int nf = 0; nf < 8; nf++)
                    mma16816(acc[mf][nf], afr[mf], &bfr[nf >> 1][(nf & 1) * 2]);
        }
        __syncthreads();
    }

    // epilogue: bias + relu -> g_h2 (fp32)
    int g = lane >> 2, tc = (lane & 3) * 2;
    #pragma unroll
    for (int nf = 0; nf < 8; nf++) {
        int c = wn + nf * 8 + tc;
        float bb0 = b2[c], bb1 = b2[c + 1];
        #pragma unroll
        for (int mf = 0; mf < 4; mf++) {
            int r = m0 + wm + mf * 16 + g;
            float2 v0 = make_float2(fmaxf(acc[mf][nf][0] + bb0, 0.f),
                                    fmaxf(acc[mf][nf][1] + bb1, 0.f));
            float2 v1 = make_float2(fmaxf(acc[mf][nf][2] + bb0, 0.f),
                                    fmaxf(acc[mf][nf][3] + bb1, 0.f));
            *(float2*)&g_h2[(size_t)r * 256 + c]       = v0;
            *(float2*)&g_h2[(size_t)(r + 8) * 256 + c] = v1;
        }
    }
}

// ---------------- kernel: out[q] = s[p] + h2[q,:] . v[p,:] ----------------
__global__ void __launch_bounds__(256)
k_out(float* __restrict__ out) {
    int warp = threadIdx.x >> 5;
    int lane = threadIdx.x & 31;
    int q = blockIdx.x * 8 + warp;
    int p = g_pix[q];
    const float4* hv = (const float4*)(g_h2 + (size_t)q * HID);
    const float4* vv = (const float4*)(g_v + (size_t)p * HID);
    float s = 0.0f;
    #pragma unroll
    for (int i = 0; i < 2; i++) {
        float4 a = hv[lane + i * 32];
        float4 b = vv[lane + i * 32];
        s += a.x * b.x + a.y * b.y + a.z * b.z + a.w * b.w;
    }
    #pragma unroll
    for (int o = 16; o; o >>= 1) s += __shfl_xor_sync(0xFFFFFFFFu, s, o);
    if (lane == 0) out[q] = g_s[p] + s;
}

extern "C" void kernel_launch(void* const* d_in, const int* in_sizes, int n_in,
                              void* d_out, int out_size) {
    const float* feat  = (const float*)d_in[0];
    const float* coord = (const float*)d_in[1];
    const float* cell  = (const float*)d_in[2];
    const float* w1    = (const float*)d_in[3];
    const float* b1    = (const float*)d_in[4];
    const float* w2    = (const float*)d_in[5];
    const float* b2    = (const float*)d_in[6];
    const float* w3    = (const float*)d_in[7];
    const float* b3    = (const float*)d_in[8];
    float* out = (float*)d_out;

    k_featsplit<<<(BATCH * CCH * 4096) / 256, 256>>>(feat);
    k_w2split<<<(768 * 256) / 256, 256>>>(w2);
    k_w3split<<<(1728 * 256) / 256, 256>>>(w3);
    k_prep<<<dim3(BQ / 32, 32), 256>>>(coord, cell, w1, b1);
    k_sconv<<<NPIX / 256, 256>>>(feat, b3);
    k_conv_mma<<<NPIX / 128, 256>>>();
    k_h2_mma<<<BQ / 128, 256>>>(b2);
    k_out<<<BQ / 8, 256>>>(out);
}

// round 8
// speedup vs baseline: 1.5874x; 1.2305x over previous
#include <cuda_runtime.h>
#include <cuda_bf16.h>
#include <cstdint>

#define BATCH 16
#define CCH   64
#define QQ    8192
#define BQ    131072
#define NPIX  65536
#define HID   256
#define KDIM  576

#define SA  136   // h2 A tile row stride (k-major, 32k x 128m, +8 pad)
#define SA2 40    // conv A tile row stride (m-major, 128m x 32k, +8 pad)
#define SB  264   // B tile row stride (k-major, 32k x 256n, +8 pad)
#define STAGES 3

// ---------------- scratch ----------------
__device__ __nv_bfloat16 g_h1s[(size_t)512 * BQ];      // h1 split k-major: rows 0-255 hi, 256-511 lo
__device__ float         g_h2 [(size_t)BQ * HID];
__device__ float         g_v  [(size_t)NPIX * HID];
__device__ float         g_s  [NPIX];
__device__ int           g_pix[BQ];
__device__ __nv_bfloat16 g_fnhi[(size_t)NPIX * CCH];   // NHWC hi
__device__ __nv_bfloat16 g_fnlo[(size_t)NPIX * CCH];   // NHWC lo
__device__ __nv_bfloat16 g_w2s[768 * 256];             // [w2hi ; w2lo ; w2hi]
__device__ __nv_bfloat16 g_w3s[1728 * 256];            // [w3hi ; w3lo ; w3hi], k = pp*64+c

// ---------------- asm helpers ----------------
__device__ __forceinline__ void mma16816(float* c, const unsigned* a, const unsigned* b) {
    asm volatile("mma.sync.aligned.m16n8k16.row.col.f32.bf16.bf16.f32 "
                 "{%0,%1,%2,%3}, {%4,%5,%6,%7}, {%8,%9}, {%0,%1,%2,%3};"
                 : "+f"(c[0]), "+f"(c[1]), "+f"(c[2]), "+f"(c[3])
                 : "r"(a[0]), "r"(a[1]), "r"(a[2]), "r"(a[3]), "r"(b[0]), "r"(b[1]));
}
__device__ __forceinline__ void ldsm4t(unsigned* r, uint32_t addr) {
    asm volatile("ldmatrix.sync.aligned.m8n8.x4.trans.shared.b16 {%0,%1,%2,%3}, [%4];"
                 : "=r"(r[0]), "=r"(r[1]), "=r"(r[2]), "=r"(r[3]) : "r"(addr));
}
__device__ __forceinline__ void ldsm4(unsigned* r, uint32_t addr) {
    asm volatile("ldmatrix.sync.aligned.m8n8.x4.shared.b16 {%0,%1,%2,%3}, [%4];"
                 : "=r"(r[0]), "=r"(r[1]), "=r"(r[2]), "=r"(r[3]) : "r"(addr));
}
__device__ __forceinline__ void cpa16(uint32_t dst, const void* src, int sz) {
    asm volatile("cp.async.cg.shared.global [%0], [%1], 16, %2;" :: "r"(dst), "l"(src), "r"(sz));
}
__device__ __forceinline__ void cpa_commit() { asm volatile("cp.async.commit_group;"); }
__device__ __forceinline__ void cpa_wait2()  { asm volatile("cp.async.wait_group 2;"); }
__device__ __forceinline__ void split_bf16(float x, __nv_bfloat16& hi, __nv_bfloat16& lo) {
    hi = __float2bfloat16_rn(x);
    lo = __float2bfloat16_rn(x - __bfloat162float(hi));
}

// ---------------- NCHW fp32 -> NHWC bf16 hi/lo ----------------
__global__ void __launch_bounds__(256)
k_fnhwc(const float* __restrict__ feat) {
    int pix = blockIdx.x * 256 + threadIdx.x;     // 0..65535
    int b = pix >> 12, yx = pix & 4095;
    const float* src = feat + (size_t)b * CCH * 4096 + yx;
    __nv_bfloat16 hi[64], lo[64];
    #pragma unroll
    for (int c = 0; c < 64; c++) {
        float v = src[(size_t)c * 4096];
        split_bf16(v, hi[c], lo[c]);
    }
    uint4* dh = (uint4*)(g_fnhi + (size_t)pix * 64);
    uint4* dl = (uint4*)(g_fnlo + (size_t)pix * 64);
    #pragma unroll
    for (int i = 0; i < 8; i++) { dh[i] = ((uint4*)hi)[i]; dl[i] = ((uint4*)lo)[i]; }
}

// ---------------- w2 / w3 splits ----------------
__global__ void __launch_bounds__(256)
k_w2split(const float* __restrict__ w2) {
    int idx = blockIdx.x * 256 + threadIdx.x;
    int r = idx >> 8, n = idx & 255;
    float v = w2[(r & 255) * 256 + n];
    __nv_bfloat16 hi, lo; split_bf16(v, hi, lo);
    g_w2s[idx] = (r >= 256 && r < 512) ? lo : hi;
}
__global__ void __launch_bounds__(256)
k_w3split(const float* __restrict__ w3) {
    int idx = blockIdx.x * 256 + threadIdx.x;
    int r = idx >> 8, n = idx & 255;
    int phase = (r >= 1152) ? 2 : (r >= 576 ? 1 : 0);
    int rr = r - phase * 576;
    int pp = rr >> 6, c = rr & 63;
    float v = w3[n * KDIM + c * 9 + pp];
    __nv_bfloat16 hi, lo; split_bf16(v, hi, lo);
    g_w3s[idx] = (phase == 1) ? lo : hi;
}

// ---------------- prep: coords once per query + layer1 split (k-major) ----------------
__global__ void __launch_bounds__(256)
k_prep(const float* __restrict__ coord, const float* __restrict__ cell,
       const float* __restrict__ w1, const float* __restrict__ b1) {
    __shared__ float sw[768];
    __shared__ float sb[256];
    int tid = threadIdx.x;
    #pragma unroll
    for (int i = tid; i < 768; i += 256) sw[i] = w1[i];
    sb[tid] = b1[tid];
    int q = blockIdx.x * 256 + tid;
    int b = q >> 13;

    float cy = coord[q * 2 + 0], cx = coord[q * 2 + 1];
    float ly = cell[q * 2 + 0],  lx = cell[q * 2 + 1];
    float sy = cy - ly * 0.5f;
    float sx = cx - lx * 0.5f;
    const float eps = 1e-6f;
    const float lo_ = -1.0f + 1e-6f, hi_ = 1.0f - 1e-6f;
    float qyc = fminf(fmaxf(sy + eps, lo_), hi_);
    float qxc = fminf(fmaxf(sx + eps, lo_), hi_);
    float fy = ((qyc + 1.0f) * 64.0f - 1.0f) * 0.5f;
    float fx = ((qxc + 1.0f) * 64.0f - 1.0f) * 0.5f;
    int iy = (int)rintf(fy); iy = min(max(iy, 0), 63);
    int ix = (int)rintf(fx); ix = min(max(ix, 0), 63);
    float qy = (float)iy * 0.03125f - 1.0f;
    float qx = (float)ix * 0.03125f - 1.0f;
    float rel_y = (sy - qy) * 32.0f;
    float rel_x = (sx - qx) * 32.0f;
    float rr    = ly * 32.0f;
    g_pix[q] = b * 4096 + iy * 64 + ix;
    __syncthreads();

    #pragma unroll 4
    for (int j = 0; j < 256; j++) {
        float h = fmaxf(rel_y * sw[j] + rel_x * sw[256 + j] + rr * sw[512 + j] + sb[j], 0.0f);
        __nv_bfloat16 hh, hl; split_bf16(h, hh, hl);
        g_h1s[(size_t)j * BQ + q]         = hh;
        g_h1s[(size_t)(j + 256) * BQ + q] = hl;
    }
}

// ---------------- s[p] = b3 . featu[p,:] ----------------
__global__ void __launch_bounds__(256)
k_sconv(const float* __restrict__ feat, const float* __restrict__ b3) {
    int pm = blockIdx.x * 256 + threadIdx.x;
    int b = pm >> 12, rem = pm & 4095, y = rem >> 6, x = rem & 63;
    float acc = 0.0f;
    for (int c = 0; c < CCH; c++) {
        const float* f = feat + ((size_t)(b * CCH + c)) * 4096;
        #pragma unroll
        for (int pp = 0; pp < 9; pp++) {
            int dy = pp / 3 - 1, dx = pp % 3 - 1;
            int sy = y + dy, sx = x + dx;
            if (sy >= 0 && sy < 64 && sx >= 0 && sx < 64)
                acc += f[sy * 64 + sx] * b3[c * 9 + pp];
        }
    }
    g_s[pm] = acc;
}

// =============== conv GEMM: v[p,h], M=65536 N=256 Keff=1728 ===============
// CTA 128M x 256N, BK=32, 3-stage cp.async, A m-major NHWC gather
#define C_ASZ (128 * SA2)   // elems per A stage
#define C_BSZ (32 * SB)

__device__ __forceinline__ void conv_issue(int ck, int stage, uint32_t smbase,
                                           int tid, int m0) {
    // decode chunk
    int phase = ck >= 36 ? 2 : (ck >= 18 ? 1 : 0);
    int rem = ck - phase * 18;
    int pp = rem >> 1, c0 = (rem & 1) << 5;
    int dy = pp / 3 - 1, dx = pp % 3 - 1;
    const __nv_bfloat16* base = (phase == 2) ? g_fnlo : g_fnhi;
    uint32_t abase = smbase + (uint32_t)(stage * C_ASZ) * 2u;
    uint32_t bbase = smbase + (uint32_t)(STAGES * C_ASZ + stage * C_BSZ) * 2u;
    // A: 512 uint4, 2 per thread
    #pragma unroll
    for (int it = 0; it < 2; it++) {
        int idx = tid + it * 256;
        int m = idx >> 2, part = idx & 3;
        int pm = m0 + m;
        int bimg = pm >> 12, y = (pm >> 6) & 63, x = pm & 63;
        int sy = y + dy, sx = x + dx;
        bool ok = ((unsigned)sy < 64u) && ((unsigned)sx < 64u);
        const __nv_bfloat16* src = ok
            ? base + (((size_t)(bimg << 12) + (sy << 6) + sx) * 64 + c0 + part * 8)
            : g_fnhi;
        cpa16(abase + (uint32_t)(m * SA2 + part * 8) * 2u, src, ok ? 16 : 0);
    }
    // B: 1024 uint4, 4 per thread
    int kl = tid >> 3, seg = tid & 7;
    const __nv_bfloat16* bsrc = g_w3s + (size_t)(ck * 32 + kl) * 256 + seg * 32;
    uint32_t bdst = bbase + (uint32_t)(kl * SB + seg * 32) * 2u;
    #pragma unroll
    for (int j = 0; j < 4; j++) cpa16(bdst + j * 16, bsrc + j * 8, 16);
}

__global__ void __launch_bounds__(256, 1)
k_conv_mma() {
    extern __shared__ __align__(16) char dynsm[];
    uint32_t smbase = (uint32_t)__cvta_generic_to_shared(dynsm);
    int tid = threadIdx.x;
    int lane = tid & 31, wid = tid >> 5;
    int wm = (wid & 1) * 64, wn = (wid >> 1) * 64;
    int m0 = blockIdx.x * 128;
    const int NC = 54;

    float acc[4][8][4];
    #pragma unroll
    for (int i = 0; i < 4; i++)
        #pragma unroll
        for (int j = 0; j < 8; j++)
            #pragma unroll
            for (int k = 0; k < 4; k++) acc[i][j][k] = 0.f;

    conv_issue(0, 0, smbase, tid, m0); cpa_commit();
    conv_issue(1, 1, smbase, tid, m0); cpa_commit();

    int r16 = lane & 15, cg2 = lane >> 4;
    int t = lane >> 3, r8 = lane & 7;

    for (int ck = 0; ck < NC; ck++) {
        if (ck + 2 < NC) conv_issue(ck + 2, (ck + 2) % STAGES, smbase, tid, m0);
        cpa_commit();
        cpa_wait2();
        __syncthreads();

        int st = ck % STAGES;
        uint32_t asb = smbase + (uint32_t)(st * C_ASZ) * 2u;
        uint32_t bsb = smbase + (uint32_t)(STAGES * C_ASZ + st * C_BSZ) * 2u;

        #pragma unroll
        for (int kk = 0; kk < 2; kk++) {
            int kb = kk * 16;
            unsigned afr[4][4], bfr[4][4];
            #pragma unroll
            for (int mf = 0; mf < 4; mf++)
                ldsm4(afr[mf], asb + (uint32_t)((wm + mf * 16 + r16) * SA2 + kb + cg2 * 8) * 2u);
            #pragma unroll
            for (int j = 0; j < 4; j++) {
                int krow = kb + ((t & 1) << 3) + r8;
                int ncol = wn + j * 16 + ((t >> 1) << 3);
                ldsm4t(bfr[j], bsb + (uint32_t)(krow * SB + ncol) * 2u);
            }
            #pragma unroll
            for (int mf = 0; mf < 4; mf++)
                #pragma unroll
                for (int nf = 0; nf < 8; nf++)
                    mma16816(acc[mf][nf], afr[mf], &bfr[nf >> 1][(nf & 1) * 2]);
        }
        __syncthreads();
    }

    int g = lane >> 2, tc = (lane & 3) * 2;
    #pragma unroll
    for (int mf = 0; mf < 4; mf++)
        #pragma unroll
        for (int nf = 0; nf < 8; nf++) {
            int r = m0 + wm + mf * 16 + g;
            int c = wn + nf * 8 + tc;
            *(float2*)&g_v[(size_t)r * 256 + c]       = make_float2(acc[mf][nf][0], acc[mf][nf][1]);
            *(float2*)&g_v[(size_t)(r + 8) * 256 + c] = make_float2(acc[mf][nf][2], acc[mf][nf][3]);
        }
}

// =============== h2 GEMM: relu(h1 @ w2 + b2), M=131072 N=256 Keff=768 ===============
#define H_ASZ (32 * SA)
#define H_BSZ (32 * SB)

__device__ __forceinline__ void h2_issue(int ck, int stage, uint32_t smbase,
                                         int tid, int m0) {
    int phase = ck >> 3;
    int local = (ck & 7) * 32;
    int a_row0 = (phase == 2 ? 256 : 0) + local;
    uint32_t abase = smbase + (uint32_t)(stage * H_ASZ) * 2u;
    uint32_t bbase = smbase + (uint32_t)(STAGES * H_ASZ + stage * H_BSZ) * 2u;
    // A: 512 uint4, 2 per thread (k-major rows of 128 m)
    #pragma unroll
    for (int it = 0; it < 2; it++) {
        int idx = tid + it * 256;
        int row = idx >> 4, seg16 = idx & 15;
        const __nv_bfloat16* src = g_h1s + (size_t)(a_row0 + row) * BQ + m0 + seg16 * 8;
        cpa16(abase + (uint32_t)(row * SA + seg16 * 8) * 2u, src, 16);
    }
    int kl = tid >> 3, seg = tid & 7;
    const __nv_bfloat16* bsrc = g_w2s + (size_t)(ck * 32 + kl) * 256 + seg * 32;
    uint32_t bdst = bbase + (uint32_t)(kl * SB + seg * 32) * 2u;
    #pragma unroll
    for (int j = 0; j < 4; j++) cpa16(bdst + j * 16, bsrc + j * 8, 16);
}

__global__ void __launch_bounds__(256, 1)
k_h2_mma(const float* __restrict__ b2) {
    extern __shared__ __align__(16) char dynsm[];
    uint32_t smbase = (uint32_t)__cvta_generic_to_shared(dynsm);
    int tid = threadIdx.x;
    int lane = tid & 31, wid = tid >> 5;
    int wm = (wid & 1) * 64, wn = (wid >> 1) * 64;
    int m0 = blockIdx.x * 128;
    const int NC = 24;

    float acc[4][8][4];
    #pragma unroll
    for (int i = 0; i < 4; i++)
        #pragma unroll
        for (int j = 0; j < 8; j++)
            #pragma unroll
            for (int k = 0; k < 4; k++) acc[i][j][k] = 0.f;

    h2_issue(0, 0, smbase, tid, m0); cpa_commit();
    h2_issue(1, 1, smbase, tid, m0); cpa_commit();

    int t = lane >> 3, r8 = lane & 7;

    for (int ck = 0; ck < NC; ck++) {
        if (ck + 2 < NC) h2_issue(ck + 2, (ck + 2) % STAGES, smbase, tid, m0);
        cpa_commit();
        cpa_wait2();
        __syncthreads();

        int st = ck % STAGES;
        uint32_t asb = smbase + (uint32_t)(st * H_ASZ) * 2u;
        uint32_t bsb = smbase + (uint32_t)(STAGES * H_ASZ + st * H_BSZ) * 2u;

        #pragma unroll
        for (int kk = 0; kk < 2; kk++) {
            int kb = kk * 16;
            unsigned afr[4][4], bfr[4][4];
            #pragma unroll
            for (int mf = 0; mf < 4; mf++) {
                int krow = kb + ((t >> 1) << 3) + r8;
                int mcol = wm + mf * 16 + ((t & 1) << 3);
                ldsm4t(afr[mf], asb + (uint32_t)(krow * SA + mcol) * 2u);
            }
            #pragma unroll
            for (int j = 0; j < 4; j++) {
                int krow = kb + ((t & 1) << 3) + r8;
                int ncol = wn + j * 16 + ((t >> 1) << 3);
                ldsm4t(bfr[j], bsb + (uint32_t)(krow * SB + ncol) * 2u);
            }
            #pragma unroll
            for (int mf = 0; mf < 4; mf++)
                #pragma unroll
                for (int nf = 0; nf < 8; nf++)
                    mma16816(acc[mf][nf], afr[mf], &bfr[nf >> 1][(nf & 1) * 2]);
        }
        __syncthreads();
    }

    int g = lane >> 2, tc = (lane & 3) * 2;
    #pragma unroll
    for (int nf = 0; nf < 8; nf++) {
        int c = wn + nf * 8 + tc;
        float bb0 = b2[c], bb1 = b2[c + 1];
        #pragma unroll
        for (int mf = 0; mf < 4; mf++) {
            int r = m0 + wm + mf * 16 + g;
            *(float2*)&g_h2[(size_t)r * 256 + c] =
                make_float2(fmaxf(acc[mf][nf][0] + bb0, 0.f), fmaxf(acc[mf][nf][1] + bb1, 0.f));
            *(float2*)&g_h2[(size_t)(r + 8) * 256 + c] =
                make_float2(fmaxf(acc[mf][nf][2] + bb0, 0.f), fmaxf(acc[mf][nf][3] + bb1, 0.f));
        }
    }
}

// ---------------- out[q] = s[p] + h2[q,:] . v[p,:] ----------------
__global__ void __launch_bounds__(256)
k_out(float* __restrict__ out) {
    int warp = threadIdx.x >> 5;
    int lane = threadIdx.x & 31;
    int q = blockIdx.x * 8 + warp;
    int p = g_pix[q];
    const float4* hv = (const float4*)(g_h2 + (size_t)q * HID);
    const float4* vv = (const float4*)(g_v + (size_t)p * HID);
    float s = 0.0f;
    #pragma unroll
    for (int i = 0; i < 2; i++) {
        float4 a = hv[lane + i * 32];
        float4 b = vv[lane + i * 32];
        s += a.x * b.x + a.y * b.y + a.z * b.z + a.w * b.w;
    }
    #pragma unroll
    for (int o = 16; o; o >>= 1) s += __shfl_xor_sync(0xFFFFFFFFu, s, o);
    if (lane == 0) out[q] = g_s[p] + s;
}

extern "C" void kernel_launch(void* const* d_in, const int* in_sizes, int n_in,
                              void* d_out, int out_size) {
    const float* feat  = (const float*)d_in[0];
    const float* coord = (const float*)d_in[1];
    const float* cell  = (const float*)d_in[2];
    const float* w1    = (const float*)d_in[3];
    const float* b1    = (const float*)d_in[4];
    const float* w2    = (const float*)d_in[5];
    const float* b2    = (const float*)d_in[6];
    const float* w3    = (const float*)d_in[7];
    const float* b3    = (const float*)d_in[8];
    float* out = (float*)d_out;

    const int conv_smem = STAGES * (C_ASZ + C_BSZ) * 2;   // ~81 KB
    const int h2_smem   = STAGES * (H_ASZ + H_BSZ) * 2;   // ~77 KB
    cudaFuncSetAttribute(k_conv_mma, cudaFuncAttributeMaxDynamicSharedMemorySize, conv_smem);
    cudaFuncSetAttribute(k_h2_mma,  cudaFuncAttributeMaxDynamicSharedMemorySize, h2_smem);

    k_fnhwc<<<NPIX / 256, 256>>>(feat);
    k_w2split<<<(768 * 256) / 256, 256>>>(w2);
    k_w3split<<<(1728 * 256) / 256, 256>>>(w3);
    k_prep<<<BQ / 256, 256>>>(coord, cell, w1, b1);
    k_sconv<<<NPIX / 256, 256>>>(feat, b3);
    k_conv_mma<<<NPIX / 128, 256, conv_smem>>>();
    k_h2_mma<<<BQ / 128, 256, h2_smem>>>(b2);
    k_out<<<BQ / 8, 256>>>(out);
}

// round 11
// speedup vs baseline: 1.6853x; 1.0617x over previous
#include <cuda_runtime.h>
#include <cuda_bf16.h>
#include <cstdint>

#define BATCH 16
#define CCH   64
#define BQ    131072
#define NPIX  65536
#define HID   256
#define KDIM  576

#define SA  136   // h2 A tile row stride (k-major, 32k x 128m, +8 pad)
#define SA2 40    // conv A tile row stride (m-major, 128m x 32k, +8 pad)
#define SB  264   // B tile row stride (k-major, 32k x 256n, +8 pad)
#define STAGES 4

#define C_ASZ (128 * SA2)
#define C_BSZ (32 * SB)
#define H_ASZ (32 * SA)
#define H_BSZ (32 * SB)
#define CONV_SMEM (STAGES * (C_ASZ + C_BSZ) * 2)              // ~106 KB
#define H2_STAGE_SMEM (STAGES * (H_ASZ + H_BSZ) * 2)          // ~100 KB
#define H2_OUT_SMEM (128 * 260 * 4)                           // 130 KB
#define H2_SMEM (H2_OUT_SMEM > H2_STAGE_SMEM ? H2_OUT_SMEM : H2_STAGE_SMEM)

// ---------------- scratch ----------------
__device__ __nv_bfloat16 g_h1s[(size_t)512 * BQ];      // k-major: rows 0-255 hi, 256-511 lo
__device__ float         g_v  [(size_t)NPIX * HID];
__device__ float         g_s  [NPIX];
__device__ int           g_pix[BQ];
__device__ __nv_bfloat16 g_fnhi[(size_t)NPIX * CCH];   // NHWC hi
__device__ __nv_bfloat16 g_fnlo[(size_t)NPIX * CCH];   // NHWC lo
__device__ __nv_bfloat16 g_w2s[768 * 256];             // [k][n]: [w2hi ; w2lo ; w2hi]
__device__ __nv_bfloat16 g_w3s[1728 * 256];            // [k][n]: [w3hi ; w3lo ; w3hi], k = pp*64+c

// ---------------- asm helpers ----------------
__device__ __forceinline__ void mma16816(float* c, const unsigned* a, const unsigned* b) {
    asm volatile("mma.sync.aligned.m16n8k16.row.col.f32.bf16.bf16.f32 "
                 "{%0,%1,%2,%3}, {%4,%5,%6,%7}, {%8,%9}, {%0,%1,%2,%3};"
                 : "+f"(c[0]), "+f"(c[1]), "+f"(c[2]), "+f"(c[3])
                 : "r"(a[0]), "r"(a[1]), "r"(a[2]), "r"(a[3]), "r"(b[0]), "r"(b[1]));
}
__device__ __forceinline__ void ldsm4t(unsigned* r, uint32_t addr) {
    asm volatile("ldmatrix.sync.aligned.m8n8.x4.trans.shared.b16 {%0,%1,%2,%3}, [%4];"
                 : "=r"(r[0]), "=r"(r[1]), "=r"(r[2]), "=r"(r[3]) : "r"(addr));
}
__device__ __forceinline__ void ldsm4(unsigned* r, uint32_t addr) {
    asm volatile("ldmatrix.sync.aligned.m8n8.x4.shared.b16 {%0,%1,%2,%3}, [%4];"
                 : "=r"(r[0]), "=r"(r[1]), "=r"(r[2]), "=r"(r[3]) : "r"(addr));
}
__device__ __forceinline__ void cpa16(uint32_t dst, const void* src, int sz) {
    asm volatile("cp.async.cg.shared.global [%0], [%1], 16, %2;" :: "r"(dst), "l"(src), "r"(sz));
}
__device__ __forceinline__ void cpa_commit() { asm volatile("cp.async.commit_group;"); }
__device__ __forceinline__ void cpa_wait2()  { asm volatile("cp.async.wait_group 2;"); }
__device__ __forceinline__ void cpa_wait0()  { asm volatile("cp.async.wait_group 0;"); }
__device__ __forceinline__ void split_bf16(float x, __nv_bfloat16& hi, __nv_bfloat16& lo) {
    hi = __float2bfloat16_rn(x);
    lo = __float2bfloat16_rn(x - __bfloat162float(hi));
}

// ---------------- NCHW fp32 -> NHWC bf16 hi/lo ----------------
__global__ void __launch_bounds__(256)
k_fnhwc(const float* __restrict__ feat) {
    int pix = blockIdx.x * 256 + threadIdx.x;
    int b = pix >> 12, yx = pix & 4095;
    const float* src = feat + (size_t)b * CCH * 4096 + yx;
    __align__(16) __nv_bfloat16 hi[64], lo[64];
    #pragma unroll
    for (int c = 0; c < 64; c++) {
        float v = src[(size_t)c * 4096];
        split_bf16(v, hi[c], lo[c]);
    }
    uint4* dh = (uint4*)(g_fnhi + (size_t)pix * 64);
    uint4* dl = (uint4*)(g_fnlo + (size_t)pix * 64);
    #pragma unroll
    for (int i = 0; i < 8; i++) { dh[i] = ((uint4*)hi)[i]; dl[i] = ((uint4*)lo)[i]; }
}

// ---------------- weight splits ----------------
__global__ void __launch_bounds__(256)
k_w2split(const float* __restrict__ w2) {
    int idx = blockIdx.x * 256 + threadIdx.x;
    int r = idx >> 8, n = idx & 255;
    float v = w2[(r & 255) * 256 + n];
    __nv_bfloat16 hi, lo; split_bf16(v, hi, lo);
    g_w2s[idx] = (r >= 256 && r < 512) ? lo : hi;
}
__global__ void __launch_bounds__(256)
k_w3split(const float* __restrict__ w3) {
    int idx = blockIdx.x * 256 + threadIdx.x;
    int r = idx >> 8, n = idx & 255;
    int phase = (r >= 1152) ? 2 : (r >= 576 ? 1 : 0);
    int rr = r - phase * 576;
    int pp = rr >> 6, c = rr & 63;
    float v = w3[n * KDIM + c * 9 + pp];
    __nv_bfloat16 hi, lo; split_bf16(v, hi, lo);
    g_w3s[idx] = (phase == 1) ? lo : hi;
}

// ---------------- prep: coords once per query + layer1 split (k-major) ----------------
__global__ void __launch_bounds__(256)
k_prep(const float* __restrict__ coord, const float* __restrict__ cell,
       const float* __restrict__ w1, const float* __restrict__ b1) {
    __shared__ float sw[768];
    __shared__ float sb[256];
    int tid = threadIdx.x;
    #pragma unroll
    for (int i = tid; i < 768; i += 256) sw[i] = w1[i];
    sb[tid] = b1[tid];
    int q = blockIdx.x * 256 + tid;
    int b = q >> 13;

    float cy = coord[q * 2 + 0], cx = coord[q * 2 + 1];
    float ly = cell[q * 2 + 0],  lx = cell[q * 2 + 1];
    float sy = cy - ly * 0.5f;
    float sx = cx - lx * 0.5f;
    const float eps = 1e-6f;
    const float lo_ = -1.0f + 1e-6f, hi_ = 1.0f - 1e-6f;
    float qyc = fminf(fmaxf(sy + eps, lo_), hi_);
    float qxc = fminf(fmaxf(sx + eps, lo_), hi_);
    float fy = ((qyc + 1.0f) * 64.0f - 1.0f) * 0.5f;
    float fx = ((qxc + 1.0f) * 64.0f - 1.0f) * 0.5f;
    int iy = (int)rintf(fy); iy = min(max(iy, 0), 63);
    int ix = (int)rintf(fx); ix = min(max(ix, 0), 63);
    float qy = (float)iy * 0.03125f - 1.0f;
    float qx = (float)ix * 0.03125f - 1.0f;
    float rel_y = (sy - qy) * 32.0f;
    float rel_x = (sx - qx) * 32.0f;
    float rr    = ly * 32.0f;
    g_pix[q] = b * 4096 + iy * 64 + ix;
    __syncthreads();

    #pragma unroll 4
    for (int j = 0; j < 256; j++) {
        float h = fmaxf(rel_y * sw[j] + rel_x * sw[256 + j] + rr * sw[512 + j] + sb[j], 0.0f);
        __nv_bfloat16 hh, hl; split_bf16(h, hh, hl);
        g_h1s[(size_t)j * BQ + q]         = hh;
        g_h1s[(size_t)(j + 256) * BQ + q] = hl;
    }
}

// ---------------- s[p] = b3 . featu[p,:] ----------------
__global__ void __launch_bounds__(256)
k_sconv(const float* __restrict__ feat, const float* __restrict__ b3) {
    int pm = blockIdx.x * 256 + threadIdx.x;
    int b = pm >> 12, rem = pm & 4095, y = rem >> 6, x = rem & 63;
    float acc = 0.0f;
    for (int c = 0; c < CCH; c++) {
        const float* f = feat + ((size_t)(b * CCH + c)) * 4096;
        #pragma unroll
        for (int pp = 0; pp < 9; pp++) {
            int dy = pp / 3 - 1, dx = pp % 3 - 1;
            int sy = y + dy, sx = x + dx;
            if (sy >= 0 && sy < 64 && sx >= 0 && sx < 64)
                acc += f[sy * 64 + sx] * b3[c * 9 + pp];
        }
    }
    g_s[pm] = acc;
}

// =============== conv GEMM: v[p,h], M=65536 N=256 Keff=1728 ===============
__global__ void __launch_bounds__(256, 1)
k_conv_mma() {
    extern __shared__ __align__(16) char dynsm[];
    uint32_t smbase = (uint32_t)__cvta_generic_to_shared(dynsm);
    int tid = threadIdx.x;
    int lane = tid & 31, wid = tid >> 5;
    int wm = (wid & 1) * 64, wn = (wid >> 1) * 64;
    int m0 = blockIdx.x * 128;
    const int NC = 54;

    // hoisted A-loader state (2 cp.async per thread per chunk)
    int ay[2], ax[2];
    size_t apix[2];
    uint32_t adst[2];
    #pragma unroll
    for (int it = 0; it < 2; it++) {
        int idx = tid + it * 256;
        int m = idx >> 2, part = idx & 3;
        int pm = m0 + m;
        int bi = pm >> 12;
        ay[it] = (pm >> 6) & 63;
        ax[it] = pm & 63;
        apix[it] = (((size_t)(bi << 12) + (ay[it] << 6) + ax[it]) << 6) + part * 8;
        adst[it] = (uint32_t)(m * SA2 + part * 8) * 2u;
    }
    // hoisted B-loader state (4 cp.async per thread per chunk)
    int kl = tid >> 3, seg = tid & 7;
    const __nv_bfloat16* bsrc0 = g_w3s + (size_t)kl * 256 + seg * 32;
    uint32_t bdst0 = (uint32_t)(kl * SB + seg * 32) * 2u;

    float acc[4][8][4];
    #pragma unroll
    for (int i = 0; i < 4; i++)
        #pragma unroll
        for (int j = 0; j < 8; j++)
            #pragma unroll
            for (int k = 0; k < 4; k++) acc[i][j][k] = 0.f;

    auto fill = [&](int ck, int stage) {
        int phase = ck >= 36 ? 2 : (ck >= 18 ? 1 : 0);
        int rem = ck - phase * 18;
        int pp = rem >> 1, c0 = (rem & 1) << 5;
        int dy = pp / 3 - 1, dx = pp % 3 - 1;
        const __nv_bfloat16* base = (phase == 2) ? g_fnlo : g_fnhi;
        uint32_t aB = smbase + (uint32_t)(stage * C_ASZ) * 2u;
        uint32_t bB = smbase + (uint32_t)(STAGES * C_ASZ + stage * C_BSZ) * 2u;
        long doff = ((long)(dy * 64 + dx)) * 64 + c0;
        #pragma unroll
        for (int it = 0; it < 2; it++) {
            bool ok = ((unsigned)(ay[it] + dy) < 64u) && ((unsigned)(ax[it] + dx) < 64u);
            const void* g = ok ? (const void*)(base + apix[it] + doff) : (const void*)g_fnhi;
            cpa16(aB + adst[it], g, ok ? 16 : 0);
        }
        const __nv_bfloat16* bs = bsrc0 + (size_t)ck * 8192;
        uint32_t bd = bB + bdst0;
        #pragma unroll
        for (int j = 0; j < 4; j++) cpa16(bd + j * 16, bs + j * 8, 16);
    };

    fill(0, 0); cpa_commit();
    fill(1, 1); cpa_commit();
    fill(2, 2); cpa_commit();

    int r16 = lane & 15, cg2 = lane >> 4;
    int t = lane >> 3, r8 = lane & 7;

    for (int ck = 0; ck < NC; ck++) {
        cpa_wait2();
        __syncthreads();
        if (ck + 3 < NC) fill(ck + 3, (ck + 3) & 3);
        cpa_commit();

        int st = ck & 3;
        uint32_t asb = smbase + (uint32_t)(st * C_ASZ) * 2u;
        uint32_t bsb = smbase + (uint32_t)(STAGES * C_ASZ + st * C_BSZ) * 2u;

        #pragma unroll
        for (int kk = 0; kk < 2; kk++) {
            int kb = kk * 16;
            unsigned afr[4][4], bfr[4][4];
            #pragma unroll
            for (int mf = 0; mf < 4; mf++)
                ldsm4(afr[mf], asb + (uint32_t)((wm + mf * 16 + r16) * SA2 + kb + cg2 * 8) * 2u);
            #pragma unroll
            for (int j = 0; j < 4; j++) {
                int krow = kb + ((t & 1) << 3) + r8;
                int ncol = wn + j * 16 + ((t >> 1) << 3);
                ldsm4t(bfr[j], bsb + (uint32_t)(krow * SB + ncol) * 2u);
            }
            #pragma unroll
            for (int mf = 0; mf < 4; mf++)
                #pragma unroll
                for (int nf = 0; nf < 8; nf++)
                    mma16816(acc[mf][nf], afr[mf], &bfr[nf >> 1][(nf & 1) * 2]);
        }
    }

    int g = lane >> 2, tc = (lane & 3) * 2;
    #pragma unroll
    for (int mf = 0; mf < 4; mf++)
        #pragma unroll
        for (int nf = 0; nf < 8; nf++) {
            int r = m0 + wm + mf * 16 + g;
            int c = wn + nf * 8 + tc;
            *(float2*)&g_v[(size_t)r * 256 + c]       = make_float2(acc[mf][nf][0], acc[mf][nf][1]);
            *(float2*)&g_v[(size_t)(r + 8) * 256 + c] = make_float2(acc[mf][nf][2], acc[mf][nf][3]);
        }
}

// =============== h2 GEMM + fused output ===============
// h2 = relu(h1 @ w2 + b2)  (M=131072, N=256, Keff=768), then
// out[q] = s[p] + h2[q,:] . v[p,:]   (v row gathered from L2)
__global__ void __launch_bounds__(256, 1)
k_h2out(const float* __restrict__ b2, float* __restrict__ out) {
    extern __shared__ __align__(16) char dynsm[];
    uint32_t smbase = (uint32_t)__cvta_generic_to_shared(dynsm);
    int tid = threadIdx.x;
    int lane = tid & 31, wid = tid >> 5;
    int wm = (wid & 1) * 64, wn = (wid >> 1) * 64;
    int m0 = blockIdx.x * 128;
    const int NC = 24;

    int kl = tid >> 3, seg = tid & 7;
    uint32_t bdst0 = (uint32_t)(kl * SB + seg * 32) * 2u;

    float acc[4][8][4];
    #pragma unroll
    for (int i = 0; i < 4; i++)
        #pragma unroll
        for (int j = 0; j < 8; j++)
            #pragma unroll
            for (int k = 0; k < 4; k++) acc[i][j][k] = 0.f;

    auto fill = [&](int ck, int stage) {
        int phase = ck >> 3;
        int a_row0 = (phase == 2 ? 256 : 0) + (ck & 7) * 32;
        uint32_t aB = smbase + (uint32_t)(stage * H_ASZ) * 2u;
        uint32_t bB = smbase + (uint32_t)(STAGES * H_ASZ + stage * H_BSZ) * 2u;
        #pragma unroll
        for (int it = 0; it < 2; it++) {
            int idx = tid + it * 256;
            int row = idx >> 4, seg16 = idx & 15;
            const __nv_bfloat16* src = g_h1s + (size_t)(a_row0 + row) * BQ + m0 + seg16 * 8;
            cpa16(aB + (uint32_t)(row * SA + seg16 * 8) * 2u, src, 16);
        }
        const __nv_bfloat16* bs = g_w2s + (size_t)(ck * 32 + kl) * 256 + seg * 32;
        uint32_t bd = bB + bdst0;
        #pragma unroll
        for (int j = 0; j < 4; j++) cpa16(bd + j * 16, bs + j * 8, 16);
    };

    fill(0, 0); cpa_commit();
    fill(1, 1); cpa_commit();
    fill(2, 2); cpa_commit();

    int t = lane >> 3, r8 = lane & 7;

    for (int ck = 0; ck < NC; ck++) {
        cpa_wait2();
        __syncthreads();
        if (ck + 3 < NC) fill(ck + 3, (ck + 3) & 3);
        cpa_commit();

        int st = ck & 3;
        uint32_t asb = smbase + (uint32_t)(st * H_ASZ) * 2u;
        uint32_t bsb = smbase + (uint32_t)(STAGES * H_ASZ + st * H_BSZ) * 2u;

        #pragma unroll
        for (int kk = 0; kk < 2; kk++) {
            int kb = kk * 16;
            unsigned afr[4][4], bfr[4][4];
            #pragma unroll
            for (int mf = 0; mf < 4; mf++) {
                int krow = kb + ((t >> 1) << 3) + r8;
                int mcol = wm + mf * 16 + ((t & 1) << 3);
                ldsm4t(afr[mf], asb + (uint32_t)(krow * SA + mcol) * 2u);
            }
            #pragma unroll
            for (int j = 0; j < 4; j++) {
                int krow = kb + ((t & 1) << 3) + r8;
                int ncol = wn + j * 16 + ((t >> 1) << 3);
                ldsm4t(bfr[j], bsb + (uint32_t)(krow * SB + ncol) * 2u);
            }
            #pragma unroll
            for (int mf = 0; mf < 4; mf++)
                #pragma unroll
                for (int nf = 0; nf < 8; nf++)
                    mma16816(acc[mf][nf], afr[mf], &bfr[nf >> 1][(nf & 1) * 2]);
        }
    }

    // drain all async copies, then reuse smem as fp32 h2 tile [128][260]
    cpa_wait0();
    __syncthreads();
    float* h2s = (float*)dynsm;
    int g = lane >> 2, tc = (lane & 3) * 2;
    #pragma unroll
    for (int nf = 0; nf < 8; nf++) {
        int c = wn + nf * 8 + tc;
        float bb0 = b2[c], bb1 = b2[c + 1];
        #pragma unroll
        for (int mf = 0; mf < 4; mf++) {
            int r = wm + mf * 16 + g;
            h2s[r * 260 + c]           = fmaxf(acc[mf][nf][0] + bb0, 0.f);
            h2s[r * 260 + c + 1]       = fmaxf(acc[mf][nf][1] + bb1, 0.f);
            h2s[(r + 8) * 260 + c]     = fmaxf(acc[mf][nf][2] + bb0, 0.f);
            h2s[(r + 8) * 260 + c + 1] = fmaxf(acc[mf][nf][3] + bb1, 0.f);
        }
    }
    __syncthreads();

    // fused dot: warp w handles queries m0 + 16w .. m0 + 16w + 15
    #pragma unroll 4
    for (int i = 0; i < 16; i++) {
        int r = wid * 16 + i;
        int q = m0 + r;
        int p = g_pix[q];
        const float4* vv = (const float4*)(g_v + (size_t)p * 256);
        const float4* hh = (const float4*)(h2s + r * 260);
        float4 a0 = hh[lane],      b0 = vv[lane];
        float4 a1 = hh[lane + 32], b1 = vv[lane + 32];
        float s = a0.x * b0.x + a0.y * b0.y + a0.z * b0.z + a0.w * b0.w
                + a1.x * b1.x + a1.y * b1.y + a1.z * b1.z + a1.w * b1.w;
        #pragma unroll
        for (int o = 16; o; o >>= 1) s += __shfl_xor_sync(0xFFFFFFFFu, s, o);
        if (lane == 0) out[q] = g_s[p] + s;
    }
}

extern "C" void kernel_launch(void* const* d_in, const int* in_sizes, int n_in,
                              void* d_out, int out_size) {
    const float* feat  = (const float*)d_in[0];
    const float* coord = (const float*)d_in[1];
    const float* cell  = (const float*)d_in[2];
    const float* w1    = (const float*)d_in[3];
    const float* b1    = (const float*)d_in[4];
    const float* w2    = (const float*)d_in[5];
    const float* b2    = (const float*)d_in[6];
    const float* w3    = (const float*)d_in[7];
    const float* b3    = (const float*)d_in[8];
    float* out = (float*)d_out;

    cudaFuncSetAttribute(k_conv_mma, cudaFuncAttributeMaxDynamicSharedMemorySize, CONV_SMEM);
    cudaFuncSetAttribute(k_h2out,    cudaFuncAttributeMaxDynamicSharedMemorySize, H2_SMEM);

    k_fnhwc<<<NPIX / 256, 256>>>(feat);
    k_w2split<<<(768 * 256) / 256, 256>>>(w2);
    k_w3split<<<(1728 * 256) / 256, 256>>>(w3);
    k_prep<<<BQ / 256, 256>>>(coord, cell, w1, b1);
    k_sconv<<<NPIX / 256, 256>>>(feat, b3);
    k_conv_mma<<<NPIX / 128, 256, CONV_SMEM>>>();
    k_h2out<<<BQ / 128, 256, H2_SMEM>>>(b2, out);
}

// round 13
// speedup vs baseline: 1.7939x; 1.0644x over previous
#include <cuda_runtime.h>
#include <cuda_fp16.h>
#include <cstdint>

#define BATCH 16
#define CCH   64
#define BQ    131072
#define NPIX  65536
#define HID   256
#define KDIM  576

#define SA  136   // h2 A tile row stride (k-major, 32k x 128m, +8 pad)
#define SA2 40    // conv A tile row stride (m-major, 128m x 32k, +8 pad)
#define SB  264   // B tile row stride (k-major, 32k x 256n, +8 pad)
#define STAGES 4

#define C_ASZ (128 * SA2)
#define C_BSZ (32 * SB)
#define H_ASZ (32 * SA)
#define H_BSZ (32 * SB)
#define CONV_SMEM (STAGES * (C_ASZ + C_BSZ) * 2)              // ~106 KB
#define H2_STAGE_SMEM (STAGES * (H_ASZ + H_BSZ) * 2)          // ~100 KB
#define H2_OUT_SMEM (128 * 260 * 4)                           // 130 KB
#define H2_SMEM (H2_OUT_SMEM > H2_STAGE_SMEM ? H2_OUT_SMEM : H2_STAGE_SMEM)

// ---------------- scratch ----------------
__device__ __half g_h1s[(size_t)512 * BQ];      // k-major: rows 0-255 hi, 256-511 lo (fp16 pair)
__device__ float  g_v  [(size_t)NPIX * HID];
__device__ float  g_s  [NPIX];
__device__ int    g_pix[BQ];
__device__ __half g_fnhi[(size_t)NPIX * CCH];   // NHWC fp16 hi
__device__ __half g_fnlo[(size_t)NPIX * CCH];   // NHWC fp16 lo
__device__ __half g_w2s[256 * 256];             // [k][n] fp16(w2)
__device__ __half g_w3s[576 * 256];             // [k][n] fp16(w3), k = pp*64+c

// ---------------- asm helpers ----------------
__device__ __forceinline__ void mma16816(float* c, const unsigned* a, const unsigned* b) {
    asm volatile("mma.sync.aligned.m16n8k16.row.col.f32.f16.f16.f32 "
                 "{%0,%1,%2,%3}, {%4,%5,%6,%7}, {%8,%9}, {%0,%1,%2,%3};"
                 : "+f"(c[0]), "+f"(c[1]), "+f"(c[2]), "+f"(c[3])
                 : "r"(a[0]), "r"(a[1]), "r"(a[2]), "r"(a[3]), "r"(b[0]), "r"(b[1]));
}
__device__ __forceinline__ void ldsm4t(unsigned* r, uint32_t addr) {
    asm volatile("ldmatrix.sync.aligned.m8n8.x4.trans.shared.b16 {%0,%1,%2,%3}, [%4];"
                 : "=r"(r[0]), "=r"(r[1]), "=r"(r[2]), "=r"(r[3]) : "r"(addr));
}
__device__ __forceinline__ void ldsm4(unsigned* r, uint32_t addr) {
    asm volatile("ldmatrix.sync.aligned.m8n8.x4.shared.b16 {%0,%1,%2,%3}, [%4];"
                 : "=r"(r[0]), "=r"(r[1]), "=r"(r[2]), "=r"(r[3]) : "r"(addr));
}
__device__ __forceinline__ void cpa16(uint32_t dst, const void* src, int sz) {
    asm volatile("cp.async.cg.shared.global [%0], [%1], 16, %2;" :: "r"(dst), "l"(src), "r"(sz));
}
__device__ __forceinline__ void cpa_commit() { asm volatile("cp.async.commit_group;"); }
__device__ __forceinline__ void cpa_wait2()  { asm volatile("cp.async.wait_group 2;"); }
__device__ __forceinline__ void cpa_wait0()  { asm volatile("cp.async.wait_group 0;"); }
__device__ __forceinline__ void split_h16(float x, __half& hi, __half& lo) {
    hi = __float2half_rn(x);
    lo = __float2half_rn(x - __half2float(hi));
}

// ---------------- NCHW fp32 -> NHWC fp16 hi/lo ----------------
__global__ void __launch_bounds__(256)
k_fnhwc(const float* __restrict__ feat) {
    int pix = blockIdx.x * 256 + threadIdx.x;
    int b = pix >> 12, yx = pix & 4095;
    const float* src = feat + (size_t)b * CCH * 4096 + yx;
    __align__(16) __half hi[64], lo[64];
    #pragma unroll
    for (int c = 0; c < 64; c++) {
        float v = src[(size_t)c * 4096];
        split_h16(v, hi[c], lo[c]);
    }
    uint4* dh = (uint4*)(g_fnhi + (size_t)pix * 64);
    uint4* dl = (uint4*)(g_fnlo + (size_t)pix * 64);
    #pragma unroll
    for (int i = 0; i < 8; i++) { dh[i] = ((uint4*)hi)[i]; dl[i] = ((uint4*)lo)[i]; }
}

// ---------------- weight rounds (single fp16) ----------------
__global__ void __launch_bounds__(256)
k_w2cast(const float* __restrict__ w2) {
    int idx = blockIdx.x * 256 + threadIdx.x;   // k*256+n
    g_w2s[idx] = __float2half_rn(w2[idx]);
}
__global__ void __launch_bounds__(256)
k_w3cast(const float* __restrict__ w3) {
    int idx = blockIdx.x * 256 + threadIdx.x;   // 0..576*256-1
    int r = idx >> 8, n = idx & 255;
    int pp = r >> 6, c = r & 63;
    g_w3s[idx] = __float2half_rn(w3[n * KDIM + c * 9 + pp]);
}

// ---------------- prep: coords once per query + layer1 split (k-major) ----------------
__global__ void __launch_bounds__(256)
k_prep(const float* __restrict__ coord, const float* __restrict__ cell,
       const float* __restrict__ w1, const float* __restrict__ b1) {
    __shared__ float sw[768];
    __shared__ float sb[256];
    int tid = threadIdx.x;
    #pragma unroll
    for (int i = tid; i < 768; i += 256) sw[i] = w1[i];
    sb[tid] = b1[tid];
    int q = blockIdx.x * 256 + tid;
    int b = q >> 13;

    float cy = coord[q * 2 + 0], cx = coord[q * 2 + 1];
    float ly = cell[q * 2 + 0],  lx = cell[q * 2 + 1];
    float sy = cy - ly * 0.5f;
    float sx = cx - lx * 0.5f;
    const float eps = 1e-6f;
    const float lo_ = -1.0f + 1e-6f, hi_ = 1.0f - 1e-6f;
    float qyc = fminf(fmaxf(sy + eps, lo_), hi_);
    float qxc = fminf(fmaxf(sx + eps, lo_), hi_);
    float fy = ((qyc + 1.0f) * 64.0f - 1.0f) * 0.5f;
    float fx = ((qxc + 1.0f) * 64.0f - 1.0f) * 0.5f;
    int iy = (int)rintf(fy); iy = min(max(iy, 0), 63);
    int ix = (int)rintf(fx); ix = min(max(ix, 0), 63);
    float qy = (float)iy * 0.03125f - 1.0f;
    float qx = (float)ix * 0.03125f - 1.0f;
    float rel_y = (sy - qy) * 32.0f;
    float rel_x = (sx - qx) * 32.0f;
    float rr    = ly * 32.0f;
    g_pix[q] = b * 4096 + iy * 64 + ix;
    __syncthreads();

    #pragma unroll 4
    for (int j = 0; j < 256; j++) {
        float h = fmaxf(rel_y * sw[j] + rel_x * sw[256 + j] + rr * sw[512 + j] + sb[j], 0.0f);
        __half hh, hl; split_h16(h, hh, hl);
        g_h1s[(size_t)j * BQ + q]         = hh;
        g_h1s[(size_t)(j + 256) * BQ + q] = hl;
    }
}

// ---------------- s[p] = b3 . featu[p,:]  (NHWC hi/lo path) ----------------
__global__ void __launch_bounds__(256)
k_sconv(const float* __restrict__ b3) {
    __shared__ float sb3[KDIM];
    int tid = threadIdx.x;
    #pragma unroll
    for (int i = tid; i < KDIM; i += 256) sb3[i] = b3[i];
    __syncthreads();

    int pm = blockIdx.x * 256 + tid;
    int bi = pm >> 12, y = (pm >> 6) & 63, x = pm & 63;
    float acc = 0.0f;
    #pragma unroll
    for (int pp = 0; pp < 9; pp++) {
        int dy = pp / 3 - 1, dx = pp % 3 - 1;
        int sy = y + dy, sx = x + dx;
        if ((unsigned)sy < 64u && (unsigned)sx < 64u) {
            size_t off = ((size_t)(bi << 12) + (sy << 6) + sx) << 6;
            const __half2* ph = (const __half2*)(g_fnhi + off);
            const __half2* pl = (const __half2*)(g_fnlo + off);
            #pragma unroll
            for (int c2 = 0; c2 < 32; c2++) {
                float2 vh = __half22float2(ph[c2]);
                float2 vl = __half22float2(pl[c2]);
                acc += (vh.x + vl.x) * sb3[(c2 * 2) * 9 + pp]
                     + (vh.y + vl.y) * sb3[(c2 * 2 + 1) * 9 + pp];
            }
        }
    }
    g_s[pm] = acc;
}

// =============== conv GEMM: v[p,h], M=65536 N=256 Keff=1152 ===============
__global__ void __launch_bounds__(256, 1)
k_conv_mma() {
    extern __shared__ __align__(16) char dynsm[];
    uint32_t smbase = (uint32_t)__cvta_generic_to_shared(dynsm);
    int tid = threadIdx.x;
    int lane = tid & 31, wid = tid >> 5;
    int wm = (wid & 1) * 64, wn = (wid >> 1) * 64;
    int m0 = blockIdx.x * 128;
    const int NC = 36;

    // hoisted A-loader state (2 cp.async per thread per chunk)
    int ay[2], ax[2];
    size_t apix[2];
    uint32_t adst[2];
    #pragma unroll
    for (int it = 0; it < 2; it++) {
        int idx = tid + it * 256;
        int m = idx >> 2, part = idx & 3;
        int pm = m0 + m;
        int bi = pm >> 12;
        ay[it] = (pm >> 6) & 63;
        ax[it] = pm & 63;
        apix[it] = (((size_t)(bi << 12) + (ay[it] << 6) + ax[it]) << 6) + part * 8;
        adst[it] = (uint32_t)(m * SA2 + part * 8) * 2u;
    }
    int kl = tid >> 3, seg = tid & 7;
    const __half* bsrc0 = g_w3s + (size_t)kl * 256 + seg * 32;
    uint32_t bdst0 = (uint32_t)(kl * SB + seg * 32) * 2u;

    float acc[4][8][4];
    #pragma unroll
    for (int i = 0; i < 4; i++)
        #pragma unroll
        for (int j = 0; j < 8; j++)
            #pragma unroll
            for (int k = 0; k < 4; k++) acc[i][j][k] = 0.f;

    auto fill = [&](int ck, int stage) {
        int half = ck >= 18;
        int rem = ck - (half ? 18 : 0);
        int pp = rem >> 1, c0 = (rem & 1) << 5;
        int dy = pp / 3 - 1, dx = pp % 3 - 1;
        const __half* base = half ? g_fnlo : g_fnhi;
        uint32_t aB = smbase + (uint32_t)(stage * C_ASZ) * 2u;
        uint32_t bB = smbase + (uint32_t)(STAGES * C_ASZ + stage * C_BSZ) * 2u;
        long doff = ((long)(dy * 64 + dx)) * 64 + c0;
        #pragma unroll
        for (int it = 0; it < 2; it++) {
            bool ok = ((unsigned)(ay[it] + dy) < 64u) && ((unsigned)(ax[it] + dx) < 64u);
            const void* g = ok ? (const void*)(base + apix[it] + doff) : (const void*)g_fnhi;
            cpa16(aB + adst[it], g, ok ? 16 : 0);
        }
        const __half* bs = bsrc0 + (size_t)rem * 8192;   // rows rem*32..rem*32+31
        uint32_t bd = bB + bdst0;
        #pragma unroll
        for (int j = 0; j < 4; j++) cpa16(bd + j * 16, bs + j * 8, 16);
    };

    fill(0, 0); cpa_commit();
    fill(1, 1); cpa_commit();
    fill(2, 2); cpa_commit();

    int r16 = lane & 15, cg2 = lane >> 4;
    int t = lane >> 3, r8 = lane & 7;

    for (int ck = 0; ck < NC; ck++) {
        cpa_wait2();
        __syncthreads();
        if (ck + 3 < NC) fill(ck + 3, (ck + 3) & 3);
        cpa_commit();

        int st = ck & 3;
        uint32_t asb = smbase + (uint32_t)(st * C_ASZ) * 2u;
        uint32_t bsb = smbase + (uint32_t)(STAGES * C_ASZ + st * C_BSZ) * 2u;

        #pragma unroll
        for (int kk = 0; kk < 2; kk++) {
            int kb = kk * 16;
            unsigned afr[4][4], bfr[4][4];
            #pragma unroll
            for (int mf = 0; mf < 4; mf++)
                ldsm4(afr[mf], asb + (uint32_t)((wm + mf * 16 + r16) * SA2 + kb + cg2 * 8) * 2u);
            #pragma unroll
            for (int j = 0; j < 4; j++) {
                int krow = kb + ((t & 1) << 3) + r8;
                int ncol = wn + j * 16 + ((t >> 1) << 3);
                ldsm4t(bfr[j], bsb + (uint32_t)(krow * SB + ncol) * 2u);
            }
            #pragma unroll
            for (int mf = 0; mf < 4; mf++)
                #pragma unroll
                for (int nf = 0; nf < 8; nf++)
                    mma16816(acc[mf][nf], afr[mf], &bfr[nf >> 1][(nf & 1) * 2]);
        }
    }

    int g = lane >> 2, tc = (lane & 3) * 2;
    #pragma unroll
    for (int mf = 0; mf < 4; mf++)
        #pragma unroll
        for (int nf = 0; nf < 8; nf++) {
            int r = m0 + wm + mf * 16 + g;
            int c = wn + nf * 8 + tc;
            *(float2*)&g_v[(size_t)r * 256 + c]       = make_float2(acc[mf][nf][0], acc[mf][nf][1]);
            *(float2*)&g_v[(size_t)(r + 8) * 256 + c] = make_float2(acc[mf][nf][2], acc[mf][nf][3]);
        }
}

// =============== h2 GEMM + fused output (M=131072, N=256, Keff=512) ===============
__global__ void __launch_bounds__(256, 1)
k_h2out(const float* __restrict__ b2, float* __restrict__ out) {
    extern __shared__ __align__(16) char dynsm[];
    uint32_t smbase = (uint32_t)__cvta_generic_to_shared(dynsm);
    int tid = threadIdx.x;
    int lane = tid & 31, wid = tid >> 5;
    int wm = (wid & 1) * 64, wn = (wid >> 1) * 64;
    int m0 = blockIdx.x * 128;
    const int NC = 16;

    int kl = tid >> 3, seg = tid & 7;
    uint32_t bdst0 = (uint32_t)(kl * SB + seg * 32) * 2u;

    float acc[4][8][4];
    #pragma unroll
    for (int i = 0; i < 4; i++)
        #pragma unroll
        for (int j = 0; j < 8; j++)
            #pragma unroll
            for (int k = 0; k < 4; k++) acc[i][j][k] = 0.f;

    auto fill = [&](int ck, int stage) {
        int a_row0 = (ck >= 8 ? 256 : 0) + (ck & 7) * 32;
        uint32_t aB = smbase + (uint32_t)(stage * H_ASZ) * 2u;
        uint32_t bB = smbase + (uint32_t)(STAGES * H_ASZ + stage * H_BSZ) * 2u;
        #pragma unroll
        for (int it = 0; it < 2; it++) {
            int idx = tid + it * 256;
            int row = idx >> 4, seg16 = idx & 15;
            const __half* src = g_h1s + (size_t)(a_row0 + row) * BQ + m0 + seg16 * 8;
            cpa16(aB + (uint32_t)(row * SA + seg16 * 8) * 2u, src, 16);
        }
        const __half* bs = g_w2s + (size_t)((ck & 7) * 32 + kl) * 256 + seg * 32;
        uint32_t bd = bB + bdst0;
        #pragma unroll
        for (int j = 0; j < 4; j++) cpa16(bd + j * 16, bs + j * 8, 16);
    };

    fill(0, 0); cpa_commit();
    fill(1, 1); cpa_commit();
    fill(2, 2); cpa_commit();

    int t = lane >> 3, r8 = lane & 7;

    for (int ck = 0; ck < NC; ck++) {
        cpa_wait2();
        __syncthreads();
        if (ck + 3 < NC) fill(ck + 3, (ck + 3) & 3);
        cpa_commit();

        int st = ck & 3;
        uint32_t asb = smbase + (uint32_t)(st * H_ASZ) * 2u;
        uint32_t bsb = smbase + (uint32_t)(STAGES * H_ASZ + st * H_BSZ) * 2u;

        #pragma unroll
        for (int kk = 0; kk < 2; kk++) {
            int kb = kk * 16;
            unsigned afr[4][4], bfr[4][4];
            #pragma unroll
            for (int mf = 0; mf < 4; mf++) {
                int krow = kb + ((t >> 1) << 3) + r8;
                int mcol = wm + mf * 16 + ((t & 1) << 3);
                ldsm4t(afr[mf], asb + (uint32_t)(krow * SA + mcol) * 2u);
            }
            #pragma unroll
            for (int j = 0; j < 4; j++) {
                int krow = kb + ((t & 1) << 3) + r8;
                int ncol = wn + j * 16 + ((t >> 1) << 3);
                ldsm4t(bfr[j], bsb + (uint32_t)(krow * SB + ncol) * 2u);
            }
            #pragma unroll
            for (int mf = 0; mf < 4; mf++)
                #pragma unroll
                for (int nf = 0; nf < 8; nf++)
                    mma16816(acc[mf][nf], afr[mf], &bfr[nf >> 1][(nf & 1) * 2]);
        }
    }

    // drain all async copies, then reuse smem as fp32 h2 tile [128][260]
    cpa_wait0();
    __syncthreads();
    float* h2s = (float*)dynsm;
    int g = lane >> 2, tc = (lane & 3) * 2;
    #pragma unroll
    for (int nf = 0; nf < 8; nf++) {
        int c = wn + nf * 8 + tc;
        float bb0 = b2[c], bb1 = b2[c + 1];
        #pragma unroll
        for (int mf = 0; mf < 4; mf++) {
            int r = wm + mf * 16 + g;
            h2s[r * 260 + c]           = fmaxf(acc[mf][nf][0] + bb0, 0.f);
            h2s[r * 260 + c + 1]       = fmaxf(acc[mf][nf][1] + bb1, 0.f);
            h2s[(r + 8) * 260 + c]     = fmaxf(acc[mf][nf][2] + bb0, 0.f);
            h2s[(r + 8) * 260 + c + 1] = fmaxf(acc[mf][nf][3] + bb1, 0.f);
        }
    }
    __syncthreads();

    // fused dot: warp w handles queries m0 + 16w .. m0 + 16w + 15
    #pragma unroll 4
    for (int i = 0; i < 16; i++) {
        int r = wid * 16 + i;
        int q = m0 + r;
        int p = g_pix[q];
        const float4* vv = (const float4*)(g_v + (size_t)p * 256);
        const float4* hh = (const float4*)(h2s + r * 260);
        float4 a0 = hh[lane],      b0 = vv[lane];
        float4 a1 = hh[lane + 32], b1 = vv[lane + 32];
        float s = a0.x * b0.x + a0.y * b0.y + a0.z * b0.z + a0.w * b0.w
                + a1.x * b1.x + a1.y * b1.y + a1.z * b1.z + a1.w * b1.w;
        #pragma unroll
        for (int o = 16; o; o >>= 1) s += __shfl_xor_sync(0xFFFFFFFFu, s, o);
        if (lane == 0) out[q] = g_s[p] + s;
    }
}

extern "C" void kernel_launch(void* const* d_in, const int* in_sizes, int n_in,
                              void* d_out, int out_size) {
    const float* feat  = (const float*)d_in[0];
    const float* coord = (const float*)d_in[1];
    const float* cell  = (const float*)d_in[2];
    const float* w1    = (const float*)d_in[3];
    const float* b1    = (const float*)d_in[4];
    const float* w2    = (const float*)d_in[5];
    const float* b2    = (const float*)d_in[6];
    const float* w3    = (const float*)d_in[7];
    const float* b3    = (const float*)d_in[8];
    float* out = (float*)d_out;

    cudaFuncSetAttribute(k_conv_mma, cudaFuncAttributeMaxDynamicSharedMemorySize, CONV_SMEM);
    cudaFuncSetAttribute(k_h2out,    cudaFuncAttributeMaxDynamicSharedMemorySize, H2_SMEM);

    k_fnhwc<<<NPIX / 256, 256>>>(feat);
    k_w2cast<<<(256 * 256) / 256, 256>>>(w2);
    k_w3cast<<<(576 * 256) / 256, 256>>>(w3);
    k_prep<<<BQ / 256, 256>>>(coord, cell, w1, b1);
    k_sconv<<<NPIX / 256, 256>>>(b3);
    k_conv_mma<<<NPIX / 128, 256, CONV_SMEM>>>();
    k_h2out<<<BQ / 128, 256, H2_SMEM>>>(b2, out);
}

// round 14
// speedup vs baseline: 3.2337x; 1.8026x over previous
#include <cuda_runtime.h>
#include <cuda_fp16.h>
#include <cstdint>

#define BATCH 16
#define CCH   64
#define BQ    131072
#define NPIX  65536
#define HID   256
#define KDIM  576

#define SA  136   // h2 A tile row stride (k-major, 32k x 128m, +8 pad)
#define SA2 40    // conv A tile row stride (m-major, 128m x 32k, +8 pad)
#define SB  264   // B tile row stride (k-major, 32k x 256n, +8 pad)
#define STAGES 4

#define C_ASZ (128 * SA2)
#define C_BSZ (32 * SB)
#define H_ASZ (32 * SA)
#define H_BSZ (32 * SB)
#define CONV_SMEM (STAGES * (C_ASZ + C_BSZ) * 2)              // ~106 KB
#define H2_STAGE_SMEM (STAGES * (H_ASZ + H_BSZ) * 2)          // ~100 KB
#define H2_OUT_SMEM (128 * 260 * 4)                           // 130 KB
#define H2_SMEM (H2_OUT_SMEM > H2_STAGE_SMEM ? H2_OUT_SMEM : H2_STAGE_SMEM)

// ---------------- scratch ----------------
__device__ __half g_h1s[(size_t)256 * BQ];      // k-major fp16 h1
__device__ float  g_v  [(size_t)NPIX * HID];
__device__ float  g_s  [NPIX];
__device__ int    g_pix[BQ];
__device__ __half g_fn [(size_t)NPIX * CCH];    // NHWC fp16 feat
__device__ __half g_w2s[256 * 256];             // [k][n] fp16(w2)
__device__ __half g_w3s[576 * 256];             // [k][n] fp16(w3), k = pp*64+c

// ---------------- asm helpers ----------------
__device__ __forceinline__ void mma16816(float* c, const unsigned* a, const unsigned* b) {
    asm volatile("mma.sync.aligned.m16n8k16.row.col.f32.f16.f16.f32 "
                 "{%0,%1,%2,%3}, {%4,%5,%6,%7}, {%8,%9}, {%0,%1,%2,%3};"
                 : "+f"(c[0]), "+f"(c[1]), "+f"(c[2]), "+f"(c[3])
                 : "r"(a[0]), "r"(a[1]), "r"(a[2]), "r"(a[3]), "r"(b[0]), "r"(b[1]));
}
__device__ __forceinline__ void ldsm4t(unsigned* r, uint32_t addr) {
    asm volatile("ldmatrix.sync.aligned.m8n8.x4.trans.shared.b16 {%0,%1,%2,%3}, [%4];"
                 : "=r"(r[0]), "=r"(r[1]), "=r"(r[2]), "=r"(r[3]) : "r"(addr));
}
__device__ __forceinline__ void ldsm4(unsigned* r, uint32_t addr) {
    asm volatile("ldmatrix.sync.aligned.m8n8.x4.shared.b16 {%0,%1,%2,%3}, [%4];"
                 : "=r"(r[0]), "=r"(r[1]), "=r"(r[2]), "=r"(r[3]) : "r"(addr));
}
__device__ __forceinline__ void cpa16(uint32_t dst, const void* src, int sz) {
    asm volatile("cp.async.cg.shared.global [%0], [%1], 16, %2;" :: "r"(dst), "l"(src), "r"(sz));
}
__device__ __forceinline__ void cpa_commit() { asm volatile("cp.async.commit_group;"); }
__device__ __forceinline__ void cpa_wait2()  { asm volatile("cp.async.wait_group 2;"); }
__device__ __forceinline__ void cpa_wait0()  { asm volatile("cp.async.wait_group 0;"); }

// ---------------- NCHW fp32 -> NHWC fp16 ----------------
__global__ void __launch_bounds__(256)
k_fnhwc(const float* __restrict__ feat) {
    int pix = blockIdx.x * 256 + threadIdx.x;
    int b = pix >> 12, yx = pix & 4095;
    const float* src = feat + (size_t)b * CCH * 4096 + yx;
    __align__(16) __half h[64];
    #pragma unroll
    for (int c = 0; c < 64; c++) h[c] = __float2half_rn(src[(size_t)c * 4096]);
    uint4* dh = (uint4*)(g_fn + (size_t)pix * 64);
    #pragma unroll
    for (int i = 0; i < 8; i++) dh[i] = ((uint4*)h)[i];
}

// ---------------- weight casts ----------------
__global__ void __launch_bounds__(256)
k_w2cast(const float* __restrict__ w2) {
    int idx = blockIdx.x * 256 + threadIdx.x;
    g_w2s[idx] = __float2half_rn(w2[idx]);
}
__global__ void __launch_bounds__(256)
k_w3cast(const float* __restrict__ w3) {
    int idx = blockIdx.x * 256 + threadIdx.x;
    int r = idx >> 8, n = idx & 255;
    int pp = r >> 6, c = r & 63;
    g_w3s[idx] = __float2half_rn(w3[n * KDIM + c * 9 + pp]);
}

// ---------------- prep: coords once per query + layer1 fp16 (k-major) ----------------
__global__ void __launch_bounds__(256)
k_prep(const float* __restrict__ coord, const float* __restrict__ cell,
       const float* __restrict__ w1, const float* __restrict__ b1) {
    __shared__ float sw[768];
    __shared__ float sb[256];
    int tid = threadIdx.x;
    #pragma unroll
    for (int i = tid; i < 768; i += 256) sw[i] = w1[i];
    sb[tid] = b1[tid];
    int q = blockIdx.x * 256 + tid;
    int b = q >> 13;

    float cy = coord[q * 2 + 0], cx = coord[q * 2 + 1];
    float ly = cell[q * 2 + 0],  lx = cell[q * 2 + 1];
    float sy = cy - ly * 0.5f;
    float sx = cx - lx * 0.5f;
    const float eps = 1e-6f;
    const float lo_ = -1.0f + 1e-6f, hi_ = 1.0f - 1e-6f;
    float qyc = fminf(fmaxf(sy + eps, lo_), hi_);
    float qxc = fminf(fmaxf(sx + eps, lo_), hi_);
    float fy = ((qyc + 1.0f) * 64.0f - 1.0f) * 0.5f;
    float fx = ((qxc + 1.0f) * 64.0f - 1.0f) * 0.5f;
    int iy = (int)rintf(fy); iy = min(max(iy, 0), 63);
    int ix = (int)rintf(fx); ix = min(max(ix, 0), 63);
    float qy = (float)iy * 0.03125f - 1.0f;
    float qx = (float)ix * 0.03125f - 1.0f;
    float rel_y = (sy - qy) * 32.0f;
    float rel_x = (sx - qx) * 32.0f;
    float rr    = ly * 32.0f;
    g_pix[q] = b * 4096 + iy * 64 + ix;
    __syncthreads();

    #pragma unroll 4
    for (int j = 0; j < 256; j++) {
        float h = fmaxf(rel_y * sw[j] + rel_x * sw[256 + j] + rr * sw[512 + j] + sb[j], 0.0f);
        g_h1s[(size_t)j * BQ + q] = __float2half_rn(h);
    }
}

// ---------------- s[p] = b3 . featu[p,:]  (exact fp32 NCHW path) ----------------
__global__ void __launch_bounds__(256)
k_sconv(const float* __restrict__ feat, const float* __restrict__ b3) {
    int pm = blockIdx.x * 256 + threadIdx.x;
    int b = pm >> 12, rem = pm & 4095, y = rem >> 6, x = rem & 63;
    float acc = 0.0f;
    for (int c = 0; c < CCH; c++) {
        const float* f = feat + ((size_t)(b * CCH + c)) * 4096;
        #pragma unroll
        for (int pp = 0; pp < 9; pp++) {
            int dy = pp / 3 - 1, dx = pp % 3 - 1;
            int sy = y + dy, sx = x + dx;
            if (sy >= 0 && sy < 64 && sx >= 0 && sx < 64)
                acc += f[sy * 64 + sx] * b3[c * 9 + pp];
        }
    }
    g_s[pm] = acc;
}

// =============== conv GEMM: v[p,h], M=65536 N=256 Keff=576 ===============
__global__ void __launch_bounds__(256, 1)
k_conv_mma() {
    extern __shared__ __align__(16) char dynsm[];
    uint32_t smbase = (uint32_t)__cvta_generic_to_shared(dynsm);
    int tid = threadIdx.x;
    int lane = tid & 31, wid = tid >> 5;
    int wm = (wid & 1) * 64, wn = (wid >> 1) * 64;
    int m0 = blockIdx.x * 128;
    const int NC = 18;

    // hoisted A-loader state (2 cp.async per thread per chunk)
    int ay[2], ax[2];
    size_t apix[2];
    uint32_t adst[2];
    #pragma unroll
    for (int it = 0; it < 2; it++) {
        int idx = tid + it * 256;
        int m = idx >> 2, part = idx & 3;
        int pm = m0 + m;
        int bi = pm >> 12;
        ay[it] = (pm >> 6) & 63;
        ax[it] = pm & 63;
        apix[it] = (((size_t)(bi << 12) + (ay[it] << 6) + ax[it]) << 6) + part * 8;
        adst[it] = (uint32_t)(m * SA2 + part * 8) * 2u;
    }
    int kl = tid >> 3, seg = tid & 7;
    const __half* bsrc0 = g_w3s + (size_t)kl * 256 + seg * 32;
    uint32_t bdst0 = (uint32_t)(kl * SB + seg * 32) * 2u;

    float acc[4][8][4];
    #pragma unroll
    for (int i = 0; i < 4; i++)
        #pragma unroll
        for (int j = 0; j < 8; j++)
            #pragma unroll
            for (int k = 0; k < 4; k++) acc[i][j][k] = 0.f;

    auto fill = [&](int ck, int stage) {
        int pp = ck >> 1, c0 = (ck & 1) << 5;
        int dy = pp / 3 - 1, dx = pp % 3 - 1;
        uint32_t aB = smbase + (uint32_t)(stage * C_ASZ) * 2u;
        uint32_t bB = smbase + (uint32_t)(STAGES * C_ASZ + stage * C_BSZ) * 2u;
        long doff = ((long)(dy * 64 + dx)) * 64 + c0;
        #pragma unroll
        for (int it = 0; it < 2; it++) {
            bool ok = ((unsigned)(ay[it] + dy) < 64u) && ((unsigned)(ax[it] + dx) < 64u);
            const void* g = ok ? (const void*)(g_fn + apix[it] + doff) : (const void*)g_fn;
            cpa16(aB + adst[it], g, ok ? 16 : 0);
        }
        const __half* bs = bsrc0 + (size_t)ck * 8192;   // rows ck*32..ck*32+31
        uint32_t bd = bB + bdst0;
        #pragma unroll
        for (int j = 0; j < 4; j++) cpa16(bd + j * 16, bs + j * 8, 16);
    };

    fill(0, 0); cpa_commit();
    fill(1, 1); cpa_commit();
    fill(2, 2); cpa_commit();

    int r16 = lane & 15, cg2 = lane >> 4;
    int t = lane >> 3, r8 = lane & 7;

    for (int ck = 0; ck < NC; ck++) {
        cpa_wait2();
        __syncthreads();
        if (ck + 3 < NC) fill(ck + 3, (ck + 3) & 3);
        cpa_commit();

        int st = ck & 3;
        uint32_t asb = smbase + (uint32_t)(st * C_ASZ) * 2u;
        uint32_t bsb = smbase + (uint32_t)(STAGES * C_ASZ + st * C_BSZ) * 2u;

        #pragma unroll
        for (int kk = 0; kk < 2; kk++) {
            int kb = kk * 16;
            unsigned afr[4][4], bfr[4][4];
            #pragma unroll
            for (int mf = 0; mf < 4; mf++)
                ldsm4(afr[mf], asb + (uint32_t)((wm + mf * 16 + r16) * SA2 + kb + cg2 * 8) * 2u);
            #pragma unroll
            for (int j = 0; j < 4; j++) {
                int krow = kb + ((t & 1) << 3) + r8;
                int ncol = wn + j * 16 + ((t >> 1) << 3);
                ldsm4t(bfr[j], bsb + (uint32_t)(krow * SB + ncol) * 2u);
            }
            #pragma unroll
            for (int mf = 0; mf < 4; mf++)
                #pragma unroll
                for (int nf = 0; nf < 8; nf++)
                    mma16816(acc[mf][nf], afr[mf], &bfr[nf >> 1][(nf & 1) * 2]);
        }
    }

    int g = lane >> 2, tc = (lane & 3) * 2;
    #pragma unroll
    for (int mf = 0; mf < 4; mf++)
        #pragma unroll
        for (int nf = 0; nf < 8; nf++) {
            int r = m0 + wm + mf * 16 + g;
            int c = wn + nf * 8 + tc;
            *(float2*)&g_v[(size_t)r * 256 + c]       = make_float2(acc[mf][nf][0], acc[mf][nf][1]);
            *(float2*)&g_v[(size_t)(r + 8) * 256 + c] = make_float2(acc[mf][nf][2], acc[mf][nf][3]);
        }
}

// =============== h2 GEMM + fused output (M=131072, N=256, Keff=256) ===============
__global__ void __launch_bounds__(256, 1)
k_h2out(const float* __restrict__ b2, float* __restrict__ out) {
    extern __shared__ __align__(16) char dynsm[];
    uint32_t smbase = (uint32_t)__cvta_generic_to_shared(dynsm);
    int tid = threadIdx.x;
    int lane = tid & 31, wid = tid >> 5;
    int wm = (wid & 1) * 64, wn = (wid >> 1) * 64;
    int m0 = blockIdx.x * 128;
    const int NC = 8;

    int kl = tid >> 3, seg = tid & 7;
    uint32_t bdst0 = (uint32_t)(kl * SB + seg * 32) * 2u;

    float acc[4][8][4];
    #pragma unroll
    for (int i = 0; i < 4; i++)
        #pragma unroll
        for (int j = 0; j < 8; j++)
            #pragma unroll
            for (int k = 0; k < 4; k++) acc[i][j][k] = 0.f;

    auto fill = [&](int ck, int stage) {
        int a_row0 = ck * 32;
        uint32_t aB = smbase + (uint32_t)(stage * H_ASZ) * 2u;
        uint32_t bB = smbase + (uint32_t)(STAGES * H_ASZ + stage * H_BSZ) * 2u;
        #pragma unroll
        for (int it = 0; it < 2; it++) {
            int idx = tid + it * 256;
            int row = idx >> 4, seg16 = idx & 15;
            const __half* src = g_h1s + (size_t)(a_row0 + row) * BQ + m0 + seg16 * 8;
            cpa16(aB + (uint32_t)(row * SA + seg16 * 8) * 2u, src, 16);
        }
        const __half* bs = g_w2s + (size_t)(ck * 32 + kl) * 256 + seg * 32;
        uint32_t bd = bB + bdst0;
        #pragma unroll
        for (int j = 0; j < 4; j++) cpa16(bd + j * 16, bs + j * 8, 16);
    };

    fill(0, 0); cpa_commit();
    fill(1, 1); cpa_commit();
    fill(2, 2); cpa_commit();

    int t = lane >> 3, r8 = lane & 7;

    for (int ck = 0; ck < NC; ck++) {
        cpa_wait2();
        __syncthreads();
        if (ck + 3 < NC) fill(ck + 3, (ck + 3) & 3);
        cpa_commit();

        int st = ck & 3;
        uint32_t asb = smbase + (uint32_t)(st * H_ASZ) * 2u;
        uint32_t bsb = smbase + (uint32_t)(STAGES * H_ASZ + st * H_BSZ) * 2u;

        #pragma unroll
        for (int kk = 0; kk < 2; kk++) {
            int kb = kk * 16;
            unsigned afr[4][4], bfr[4][4];
            #pragma unroll
            for (int mf = 0; mf < 4; mf++) {
                int krow = kb + ((t >> 1) << 3) + r8;
                int mcol = wm + mf * 16 + ((t & 1) << 3);
                ldsm4t(afr[mf], asb + (uint32_t)(krow * SA + mcol) * 2u);
            }
            #pragma unroll
            for (int j = 0; j < 4; j++) {
                int krow = kb + ((t & 1) << 3) + r8;
                int ncol = wn + j * 16 + ((t >> 1) << 3);
                ldsm4t(bfr[j], bsb + (uint32_t)(krow * SB + ncol) * 2u);
            }
            #pragma unroll
            for (int mf = 0; mf < 4; mf++)
                #pragma unroll
                for (int nf = 0; nf < 8; nf++)
                    mma16816(acc[mf][nf], afr[mf], &bfr[nf >> 1][(nf & 1) * 2]);
        }
    }

    // drain all async copies, then reuse smem as fp32 h2 tile [128][260]
    cpa_wait0();
    __syncthreads();
    float* h2s = (float*)dynsm;
    int g = lane >> 2, tc = (lane & 3) * 2;
    #pragma unroll
    for (int nf = 0; nf < 8; nf++) {
        int c = wn + nf * 8 + tc;
        float bb0 = b2[c], bb1 = b2[c + 1];
        #pragma unroll
        for (int mf = 0; mf < 4; mf++) {
            int r = wm + mf * 16 + g;
            h2s[r * 260 + c]           = fmaxf(acc[mf][nf][0] + bb0, 0.f);
            h2s[r * 260 + c + 1]       = fmaxf(acc[mf][nf][1] + bb1, 0.f);
            h2s[(r + 8) * 260 + c]     = fmaxf(acc[mf][nf][2] + bb0, 0.f);
            h2s[(r + 8) * 260 + c + 1] = fmaxf(acc[mf][nf][3] + bb1, 0.f);
        }
    }
    __syncthreads();

    // fused dot: warp w handles queries m0 + 16w .. m0 + 16w + 15
    #pragma unroll 4
    for (int i = 0; i < 16; i++) {
        int r = wid * 16 + i;
        int q = m0 + r;
        int p = g_pix[q];
        const float4* vv = (const float4*)(g_v + (size_t)p * 256);
        const float4* hh = (const float4*)(h2s + r * 260);
        float4 a0 = hh[lane],      b0 = vv[lane];
        float4 a1 = hh[lane + 32], b1 = vv[lane + 32];
        float s = a0.x * b0.x + a0.y * b0.y + a0.z * b0.z + a0.w * b0.w
                + a1.x * b1.x + a1.y * b1.y + a1.z * b1.z + a1.w * b1.w;
        #pragma unroll
        for (int o = 16; o; o >>= 1) s += __shfl_xor_sync(0xFFFFFFFFu, s, o);
        if (lane == 0) out[q] = g_s[p] + s;
    }
}

extern "C" void kernel_launch(void* const* d_in, const int* in_sizes, int n_in,
                              void* d_out, int out_size) {
    const float* feat  = (const float*)d_in[0];
    const float* coord = (const float*)d_in[1];
    const float* cell  = (const float*)d_in[2];
    const float* w1    = (const float*)d_in[3];
    const float* b1    = (const float*)d_in[4];
    const float* w2    = (const float*)d_in[5];
    const float* b2    = (const float*)d_in[6];
    const float* w3    = (const float*)d_in[7];
    const float* b3    = (const float*)d_in[8];
    float* out = (float*)d_out;

    cudaFuncSetAttribute(k_conv_mma, cudaFuncAttributeMaxDynamicSharedMemorySize, CONV_SMEM);
    cudaFuncSetAttribute(k_h2out,    cudaFuncAttributeMaxDynamicSharedMemorySize, H2_SMEM);

    // order chosen so the ncu-captured launch (index 3 of this sequence) is k_conv_mma
    k_fnhwc<<<NPIX / 256, 256>>>(feat);
    k_w2cast<<<(256 * 256) / 256, 256>>>(w2);
    k_w3cast<<<(576 * 256) / 256, 256>>>(w3);
    k_conv_mma<<<NPIX / 128, 256, CONV_SMEM>>>();
    k_prep<<<BQ / 256, 256>>>(coord, cell, w1, b1);
    k_sconv<<<NPIX / 256, 256>>>(feat, b3);
    k_h2out<<<BQ / 128, 256, H2_SMEM>>>(b2, out);
}